// round 12
// baseline (speedup 1.0000x reference)
#include <cuda_runtime.h>
#include <cuda_fp16.h>
#include <math.h>
#include <stdint.h>

#define Bn 4
#define Cc 256
#define Nn 4096
#define Mm (Bn*Nn)   // 16384

// ---------------- helpers ----------------
__device__ __forceinline__ uint32_t smem_u32(const void* p){
    uint32_t a;
    asm("{ .reg .u64 t; cvta.to.shared.u64 t, %1; cvt.u32.u64 %0, t; }" : "=r"(a) : "l"(p));
    return a;
}
__device__ __forceinline__ int refl(int i, int n){ return i<0 ? -i : (i>=n ? 2*n-2-i : i); }

__device__ __forceinline__ void cpasync16(uint32_t dst, const void* src){
    asm volatile("cp.async.cg.shared.global [%0], [%1], 16;" :: "r"(dst), "l"(src) : "memory");
}
__device__ __forceinline__ void ldsm4(uint32_t (&r)[4], uint32_t addr){
    asm volatile("ldmatrix.sync.aligned.m8n8.x4.shared.b16 {%0,%1,%2,%3}, [%4];"
        : "=r"(r[0]), "=r"(r[1]), "=r"(r[2]), "=r"(r[3]) : "r"(addr));
}
__device__ __forceinline__ void mma16816(float (&d)[4], const uint32_t (&a)[4], const uint32_t* b){
    asm volatile("mma.sync.aligned.m16n8k16.row.col.f32.f16.f16.f32 "
        "{%0,%1,%2,%3},{%4,%5,%6,%7},{%8,%9},{%0,%1,%2,%3};"
        : "+f"(d[0]), "+f"(d[1]), "+f"(d[2]), "+f"(d[3])
        : "r"(a[0]), "r"(a[1]), "r"(a[2]), "r"(a[3]), "r"(b[0]), "r"(b[1]));
}
__device__ __forceinline__ void split16(float v, __half &h, __half &l){
    h = __float2half(v);
    l = __float2half(v - __half2float(h));
}

// ---------------- scratch (device globals) ----------------
__device__ float d_qkg[(size_t)Mm*768];  // [row][0:256)=g, [256:512)=theta(q), [512:768)=phi(k)
__device__ float d_wy[Mm*Cc];
__device__ __half d_ah[Mm*Cc];   // activation planes (conv/gemm input)
__device__ __half d_al[Mm*Cc];
__device__ __half d_ph[Mm*Cc];   // post-relu / attention-out planes
__device__ __half d_pl[Mm*Cc];
__device__ __half d_th[Mm*Cc];   // conv output planes (pre-IN)
__device__ __half d_tl[Mm*Cc];
__device__ __half d_wbh[6*9*Cc*Cc];
__device__ __half d_wbl[6*9*Cc*Cc];
__device__ __half d_w1h[4*Cc*Cc];
__device__ __half d_w1l[4*Cc*Cc];
__device__ float d_bcat[768];    // concat bias: g_b, th_b, ph_b
__device__ float d_mk[Mm];
__device__ int   d_act[Mm];
__device__ int   d_cnt[Bn];
__device__ float d_psum[2*Bn*Cc];   // zero-init; k_statf re-zeros after use
__device__ float d_mean[Bn*Cc];
__device__ float d_rstd[Bn*Cc];

// ---------------- weight conversion fp32 -> fp16 hi/lo (+ bias concat) ----------------
__global__ void k_wconv(const float* __restrict__ rw1, const float* __restrict__ rw2,
                        const float* __restrict__ gw, const float* __restrict__ tw,
                        const float* __restrict__ pw, const float* __restrict__ Ww,
                        const float* __restrict__ gb, const float* __restrict__ tb,
                        const float* __restrict__ pb){
    int idx = blockIdx.x*256 + threadIdx.x;
    const int NC = 6*9*65536;
    if (idx < NC){
        int cv = idx / (9*65536);
        int rem = idx - cv*(9*65536);
        int tap = rem >> 16;
        int oc = rem & 65535;
        int o = oc >> 8, c = oc & 255;
        int i = cv >> 1;
        const float* rw = (cv & 1) ? rw2 : rw1;
        float v = rw[(((i*256 + o)*256 + c)*9) + tap];
        __half h, l; split16(v, h, l);
        d_wbh[idx] = h; d_wbl[idx] = l;
    } else if (idx < NC + 4*65536){
        int j = idx - NC;
        int mat = j >> 16;
        int oc = j & 65535;
        const float* src = (mat==0) ? gw : (mat==1) ? tw : (mat==2) ? pw : Ww;
        __half h, l; split16(src[oc], h, l);
        d_w1h[j] = h; d_w1l[j] = l;
    } else if (idx < NC + 4*65536 + 768){
        int j = idx - NC - 4*65536;
        int mat = j >> 8;
        const float* src = (mat==0) ? gb : (mat==1) ? tb : pb;
        d_bcat[j] = src[j & 255];
    }
}

// ---------------- x: NCHW -> fp16 hi/lo [B,N,C] ----------------
__global__ void k_xt(const float* __restrict__ x){
    __shared__ float tile[32][33];
    int b = blockIdx.z; int n0 = blockIdx.x*32, c0 = blockIdx.y*32;
    int tx = threadIdx.x, ty = threadIdx.y;
    tile[ty][tx] = x[((size_t)(b*Cc) + c0+ty)*Nn + n0+tx];
    __syncthreads();
    size_t o = ((size_t)(b*Nn) + n0+ty)*Cc + c0+tx;
    __half h, l; split16(tile[tx][ty], h, l);
    d_ah[o] = h; d_al[o] = l;
}

// ---------------- mask + active-key compaction ----------------
__global__ void k_mask(const float* __restrict__ mask){
    int b = blockIdx.x, t = threadIdx.x;
    __shared__ int sc[1024];
    const float* mb = mask + b*32*32;
    int flag[4]; int cnt = 0;
    #pragma unroll
    for (int i=0;i<4;i++){
        int n = t*4+i; int h = n>>6, w = n&63;
        float fy = h*0.5f - 0.25f, fx = w*0.5f - 0.25f;
        int y0 = (int)floorf(fy), x0 = (int)floorf(fx);
        float wy1 = fy - (float)y0, wx1 = fx - (float)x0;
        int y0c = min(max(y0,0),31), y1c = min(max(y0+1,0),31);
        int x0c = min(max(x0,0),31), x1c = min(max(x0+1,0),31);
        float v = (mb[y0c*32+x0c]*(1.f-wx1) + mb[y0c*32+x1c]*wx1)*(1.f-wy1)
                + (mb[y1c*32+x0c]*(1.f-wx1) + mb[y1c*32+x1c]*wx1)*wy1;
        float mv = (v > 0.f) ? 1.f : v;
        float a = 1.f - mv;
        float tmp = 1.f - mb[(h>>1)*32 + (w>>1)];
        float m = a * tmp;
        d_mk[b*Nn + n] = m;
        flag[i] = (m > 0.5f) ? 1 : 0;
        cnt += flag[i];
    }
    sc[t] = cnt; __syncthreads();
    for (int s=1; s<1024; s<<=1){
        int v = (t >= s) ? sc[t-s] : 0;
        __syncthreads();
        sc[t] += v;
        __syncthreads();
    }
    int base = sc[t] - cnt;
    #pragma unroll
    for (int i=0;i<4;i++) if (flag[i]) d_act[b*Nn + (base++)] = t*4+i;
    if (t == 1023) d_cnt[b] = sc[1023];
}

// ================= warp-MMA fp16 hi/lo GEMM / 3x3-reflect-conv =================
// 3-term split: AhWh + AlWh + AhWl. 256 threads, 8 warps 4x2, warp tile 32x64.
// SMEM: 64B rows + XOR swizzle, 3 stages -> 2 CTAs/SM.
// Per-warp kk/ng traversal is staggered by warp id to de-cluster the
// ldsm (smem-crossbar) and mma (tensor) phases across the 16 resident warps.
#define PLANE 8192
#define STAGE (4*PLANE)           // 32768
#define TM_SMEM_TOTAL (3*STAGE)   // 98304

__device__ __forceinline__ void tmm_load(uint32_t st,
    const __half* __restrict__ Ah, const __half* __restrict__ Al,
    const __half* __restrict__ Wh, const __half* __restrict__ Wl,
    int m0, int n0, int chunk, int ntaps, int t)
{
    int tap = chunk >> 3, k0 = (chunk & 7)*32;
    int dy = tap/3 - 1, dx = tap%3 - 1;
    #pragma unroll
    for (int it=0; it<2; it++){
        int e = t + it*256;
        int r = e >> 2, ch = e & 3;
        int slot = ch ^ ((r >> 1) & 3);
        uint32_t dst = st + r*64 + (slot << 4);
        int grow;
        if (ntaps > 1){
            int gg = m0 + r, b = gg >> 12, p = gg & 4095, h = p >> 6, w = p & 63;
            grow = (b << 12) + (refl(h+dy,64) << 6) + refl(w+dx,64);
        } else grow = m0 + r;
        size_t srcA = (size_t)grow*256 + k0 + ch*8;
        cpasync16(dst,         Ah + srcA);
        cpasync16(dst + PLANE, Al + srcA);
        size_t srcB = ((size_t)tap*256 + n0 + r)*256 + k0 + ch*8;
        cpasync16(dst + 2*PLANE, Wh + srcB);
        cpasync16(dst + 3*PLANE, Wl + srcB);
    }
}

__global__ void __launch_bounds__(256, 2)
k_tmm(const __half* __restrict__ Ah, const __half* __restrict__ Al,
      const __half* __restrict__ Wh, const __half* __restrict__ Wl,
      const float* __restrict__ bias, float* __restrict__ Cout,
      __half* __restrict__ Oh, __half* __restrict__ Ol,
      float* __restrict__ psum, int ntaps, int ldc)
{
    extern __shared__ char smem[];
    uint32_t sb = smem_u32(smem);
    int t = threadIdx.x, lane = t & 31, wid = t >> 5;
    int warp_m = wid & 3, warp_n = wid >> 2;   // 4 x 2, warp tile 32x64
    int n0 = blockIdx.x * 128, m0 = blockIdx.y * 128;
    int kks = wid & 1, ngs = (wid >> 1) & 1;   // per-warp phase stagger

    int S = ntaps * 8;
    float acc[2][8][4] = {};

    tmm_load(sb,         Ah, Al, Wh, Wl, m0, n0, 0, ntaps, t);
    asm volatile("cp.async.commit_group;" ::: "memory");
    if (S > 1){ tmm_load(sb + STAGE, Ah, Al, Wh, Wl, m0, n0, 1, ntaps, t);
                asm volatile("cp.async.commit_group;" ::: "memory"); }

    int rA  = warp_m*32 + (lane & 15);
    int hiA = lane >> 4;
    int sxA = (rA >> 1) & 3;
    uint32_t aRow = (uint32_t)rA * 64;
    int rB  = warp_n*64 + (lane & 7) + ((lane >> 4) << 3);
    int gB  = (lane >> 3) & 1;
    int sxB = (rB >> 1) & 3;
    uint32_t bRow = (uint32_t)rB * 64;

    for (int i = 0; i < S; i++){
        int rem = S - 1 - i;
        if (rem >= 1) asm volatile("cp.async.wait_group 1;" ::: "memory");
        else          asm volatile("cp.async.wait_group 0;" ::: "memory");
        __syncthreads();
        if (i + 2 < S){
            tmm_load(sb + (uint32_t)((i+2)%3)*STAGE, Ah, Al, Wh, Wl, m0, n0, i+2, ntaps, t);
            asm volatile("cp.async.commit_group;" ::: "memory");
        }
        uint32_t st = sb + (uint32_t)(i%3)*STAGE;
        #pragma unroll
        for (int kk2 = 0; kk2 < 2; kk2++){
            int kk = kk2 ^ kks;
            uint32_t aAddr = st + aRow + ((uint32_t)(((2*kk) + hiA) ^ sxA) << 4);
            uint32_t aH[2][4], aL[2][4];
            ldsm4(aH[0], aAddr);
            ldsm4(aH[1], aAddr + 16*64);
            ldsm4(aL[0], aAddr + PLANE);
            ldsm4(aL[1], aAddr + PLANE + 16*64);
            #pragma unroll
            for (int ng2 = 0; ng2 < 2; ng2++){
                int ng = ng2 ^ ngs;
                uint32_t bAddr = st + 2*PLANE + bRow + (uint32_t)(ng*32*64)
                               + ((uint32_t)(((2*kk) + gB) ^ sxB) << 4);
                uint32_t bH[8], bL[8];
                ldsm4(*(uint32_t(*)[4])&bH[0], bAddr);
                ldsm4(*(uint32_t(*)[4])&bH[4], bAddr + 16*64);
                ldsm4(*(uint32_t(*)[4])&bL[0], bAddr + PLANE);
                ldsm4(*(uint32_t(*)[4])&bL[4], bAddr + PLANE + 16*64);
                #pragma unroll
                for (int j = 0; j < 4; j++){
                    int nt = ng*4 + j;
                    #pragma unroll
                    for (int mt = 0; mt < 2; mt++)
                        mma16816(acc[mt][nt], aH[mt], &bH[2*j]);
                }
                #pragma unroll
                for (int j = 0; j < 4; j++){
                    int nt = ng*4 + j;
                    #pragma unroll
                    for (int mt = 0; mt < 2; mt++)
                        mma16816(acc[mt][nt], aH[mt], &bL[2*j]);
                }
                #pragma unroll
                for (int j = 0; j < 4; j++){
                    int nt = ng*4 + j;
                    #pragma unroll
                    for (int mt = 0; mt < 2; mt++)
                        mma16816(acc[mt][nt], aL[mt], &bH[2*j]);
                }
            }
        }
    }

    // ---- epilogue (+ fused IN stats) ----
    int rbase = m0 + warp_m*32;
    int nb = n0 + warp_n*64;
    int rr = lane >> 2, c2 = 2*(lane & 3);
    float cs[16] = {}, cs2[16] = {};
    #pragma unroll
    for (int mt = 0; mt < 2; mt++){
        #pragma unroll
        for (int nt = 0; nt < 8; nt++){
            int row = rbase + mt*16 + rr;
            int col = nb + nt*8 + c2;
            float b0 = bias[col], b1 = bias[col+1];
            float v00 = acc[mt][nt][0] + b0, v01 = acc[mt][nt][1] + b1;
            float v10 = acc[mt][nt][2] + b0, v11 = acc[mt][nt][3] + b1;
            if (Cout){
                float2 p0; p0.x = v00; p0.y = v01;
                float2 p1; p1.x = v10; p1.y = v11;
                *(float2*)&Cout[(size_t)row*ldc + col] = p0;
                *(float2*)&Cout[(size_t)(row+8)*ldc + col] = p1;
            }
            if (Oh){
                __half h00, l00, h01, l01, h10, l10, h11, l11;
                split16(v00, h00, l00); split16(v01, h01, l01);
                split16(v10, h10, l10); split16(v11, h11, l11);
                *(__half2*)&Oh[(size_t)row*256 + col]     = __halves2half2(h00, h01);
                *(__half2*)&Ol[(size_t)row*256 + col]     = __halves2half2(l00, l01);
                *(__half2*)&Oh[(size_t)(row+8)*256 + col] = __halves2half2(h10, h11);
                *(__half2*)&Ol[(size_t)(row+8)*256 + col] = __halves2half2(l10, l11);
            }
            cs [nt*2]   += v00 + v10;
            cs [nt*2+1] += v01 + v11;
            cs2[nt*2]   += v00*v00 + v10*v10;
            cs2[nt*2+1] += v01*v01 + v11*v11;
        }
    }
    if (psum){
        #pragma unroll
        for (int o = 4; o <= 16; o <<= 1){
            #pragma unroll
            for (int j = 0; j < 16; j++){
                cs[j]  += __shfl_xor_sync(0xffffffffu, cs[j],  o);
                cs2[j] += __shfl_xor_sync(0xffffffffu, cs2[j], o);
            }
        }
        if (lane < 4){
            int b = m0 >> 12;
            #pragma unroll
            for (int nt = 0; nt < 8; nt++){
                int col = nb + nt*8 + 2*lane;
                atomicAdd(&psum[b*256 + col],          cs [2*nt]);
                atomicAdd(&psum[b*256 + col + 1],      cs [2*nt+1]);
                atomicAdd(&psum[1024 + b*256 + col],   cs2[2*nt]);
                atomicAdd(&psum[1024 + b*256 + col+1], cs2[2*nt+1]);
            }
        }
    }
}

// ---------------- masked-softmax attention over compacted keys ----------------
// Reads the fused QKG buffer: [row][0:256)=g, [256:512)=q(theta), [512:768)=k(phi).
__global__ void __launch_bounds__(256) k_attn(){
    int b = blockIdx.y; int q0 = blockIdx.x * 16;
    __shared__ float Qs[16][260];
    __shared__ float Ks[16][260];
    __shared__ float Gs[16][260];
    __shared__ float Ss[16][17];
    int t = threadIdx.x;
    for (int i4 = t; i4 < 16*64; i4 += 256){
        int r = i4 >> 6, c4 = (i4 & 63) * 4;
        *(float4*)&Qs[r][c4] = *(const float4*)&d_qkg[((size_t)(b*Nn) + q0 + r)*768 + 256 + c4];
    }
    int cnt = d_cnt[b];
    int q = t >> 4, lane = t & 15;
    float yacc[16];
    #pragma unroll
    for (int i=0;i<16;i++) yacc[i] = 0.f;
    float rmax = -1e30f, rsum = 0.f;
    __syncthreads();
    for (int j0=0; j0<cnt; j0+=16){
        int jn = min(16, cnt - j0);
        for (int i4 = t; i4 < jn*64; i4 += 256){
            int r = i4 >> 6, c4 = (i4 & 63) * 4;
            int src = d_act[b*Nn + j0 + r];
            size_t base = ((size_t)(b*Nn) + src)*768;
            *(float4*)&Ks[r][c4] = *(const float4*)&d_qkg[base + 512 + c4];
            *(float4*)&Gs[r][c4] = *(const float4*)&d_qkg[base + c4];
        }
        __syncthreads();
        float s = -1e30f;
        if (lane < jn){
            s = 0.f;
            #pragma unroll 4
            for (int c4 = 0; c4 < 64; c4++){
                float4 qv = *(const float4*)&Qs[q][c4*4];
                float4 kv = *(const float4*)&Ks[lane][c4*4];
                s += qv.x*kv.x + qv.y*kv.y + qv.z*kv.z + qv.w*kv.w;
            }
        }
        Ss[q][lane] = s;
        __syncthreads();
        float cmax = rmax;
        for (int j=0;j<jn;j++) cmax = fmaxf(cmax, Ss[q][j]);
        float scale = expf(rmax - cmax);
        rsum *= scale;
        #pragma unroll
        for (int i=0;i<16;i++) yacc[i] *= scale;
        for (int j=0;j<jn;j++){
            float pj = expf(Ss[q][j] - cmax);
            rsum += pj;
            #pragma unroll
            for (int i=0;i<16;i++) yacc[i] += pj * Gs[j][lane + i*16];
        }
        rmax = cmax;
        __syncthreads();
    }
    float inv = (rsum > 0.f) ? (1.f/rsum) : 0.f;
    #pragma unroll
    for (int i=0;i<16;i++){
        float v = yacc[i]*inv;
        size_t o = ((size_t)(b*Nn) + q0 + q)*256 + lane + i*16;
        __half h, l; split16(v, h, l);
        d_ph[o] = h; d_pl[o] = l;
    }
}

// ---------------- instance-norm finalize (reads+zeros psum) ----------------
__global__ void k_statf(){
    int b = blockIdx.x, c = threadIdx.x;
    float s  = d_psum[b*256 + c];
    float s2 = d_psum[1024 + b*256 + c];
    float mu = s * (1.f/4096.f);
    float var = s2 * (1.f/4096.f) - mu*mu;
    d_mean[b*256+c] = mu;
    d_rstd[b*256+c] = rsqrtf(var + 1e-5f);
    d_psum[b*256 + c] = 0.f;
    d_psum[1024 + b*256 + c] = 0.f;
}

// relu(IN(t-planes)) -> p-planes   (2 elems/thread)
__global__ void k_in_relu(){
    int i2 = blockIdx.x*256 + threadIdx.x;
    int base = i2*2;
    int c = base & 255; int b = base >> 20;
    __half2 h2 = *(const __half2*)&d_th[base];
    __half2 l2 = *(const __half2*)&d_tl[base];
    float v0 = __half2float(h2.x) + __half2float(l2.x);
    float v1 = __half2float(h2.y) + __half2float(l2.y);
    v0 = fmaxf((v0 - d_mean[b*256+c])   * d_rstd[b*256+c],   0.f);
    v1 = fmaxf((v1 - d_mean[b*256+c+1]) * d_rstd[b*256+c+1], 0.f);
    __half h0, l0, h1, l1; split16(v0, h0, l0); split16(v1, h1, l1);
    *(__half2*)&d_ph[base] = __halves2half2(h0, h1);
    *(__half2*)&d_pl[base] = __halves2half2(l0, l1);
}
// wy += IN(t-planes); write new a-planes
__global__ void k_in_add(float* __restrict__ io){
    int i2 = blockIdx.x*256 + threadIdx.x;
    int base = i2*2;
    int c = base & 255; int b = base >> 20;
    __half2 h2 = *(const __half2*)&d_th[base];
    __half2 l2 = *(const __half2*)&d_tl[base];
    float v0 = __half2float(h2.x) + __half2float(l2.x);
    float v1 = __half2float(h2.y) + __half2float(l2.y);
    float2 w = *(float2*)&io[base];
    w.x += (v0 - d_mean[b*256+c])   * d_rstd[b*256+c];
    w.y += (v1 - d_mean[b*256+c+1]) * d_rstd[b*256+c+1];
    *(float2*)&io[base] = w;
    __half h0, l0, h1, l1; split16(w.x, h0, l0); split16(w.y, h1, l1);
    *(__half2*)&d_ah[base] = __halves2half2(h0, h1);
    *(__half2*)&d_al[base] = __halves2half2(l0, l1);
}

// ---------------- final blend + NHWC->NCHW ----------------
__global__ void k_blend(const float* __restrict__ x, float* __restrict__ z){
    __shared__ float tile[32][33];
    int b = blockIdx.z; int n0 = blockIdx.x*32, c0 = blockIdx.y*32;
    int tx = threadIdx.x, ty = threadIdx.y;
    tile[ty][tx] = d_wy[((size_t)(b*Nn) + n0+ty)*256 + c0+tx];
    __syncthreads();
    int n = n0 + tx, c = c0 + ty;
    float m = d_mk[b*Nn + n];
    size_t idx = ((size_t)(b*Cc + c))*Nn + n;
    z[idx] = m * x[idx] + (1.f - m) * tile[tx][ty];
}

// ---------------- launch ----------------
extern "C" void kernel_launch(void* const* d_in, const int* in_sizes, int n_in,
                              void* d_out, int out_size) {
    (void)in_sizes; (void)n_in; (void)out_size;
    const float* x    = (const float*)d_in[0];
    const float* mask = (const float*)d_in[1];
    const float* g_w  = (const float*)d_in[2];
    const float* g_b  = (const float*)d_in[3];
    const float* th_w = (const float*)d_in[4];
    const float* th_b = (const float*)d_in[5];
    const float* ph_w = (const float*)d_in[6];
    const float* ph_b = (const float*)d_in[7];
    const float* W_w  = (const float*)d_in[8];
    const float* W_b  = (const float*)d_in[9];
    const float* rw1  = (const float*)d_in[10];
    const float* rb1  = (const float*)d_in[11];
    const float* rw2  = (const float*)d_in[12];
    const float* rb2  = (const float*)d_in[13];
    float* z = (float*)d_out;

    cudaFuncSetAttribute(k_tmm, cudaFuncAttributeMaxDynamicSharedMemorySize, TM_SMEM_TOTAL);

    float *pqkg, *pwy, *pps, *pbc;
    __half *pah, *pal, *pph, *ppl, *pth, *ptl, *pwbh, *pwbl, *pw1h, *pw1l;
    cudaGetSymbolAddress((void**)&pqkg, d_qkg);
    cudaGetSymbolAddress((void**)&pwy, d_wy);
    cudaGetSymbolAddress((void**)&pps, d_psum);
    cudaGetSymbolAddress((void**)&pbc, d_bcat);
    cudaGetSymbolAddress((void**)&pah, d_ah);
    cudaGetSymbolAddress((void**)&pal, d_al);
    cudaGetSymbolAddress((void**)&pph, d_ph);
    cudaGetSymbolAddress((void**)&ppl, d_pl);
    cudaGetSymbolAddress((void**)&pth, d_th);
    cudaGetSymbolAddress((void**)&ptl, d_tl);
    cudaGetSymbolAddress((void**)&pwbh, d_wbh);
    cudaGetSymbolAddress((void**)&pwbl, d_wbl);
    cudaGetSymbolAddress((void**)&pw1h, d_w1h);
    cudaGetSymbolAddress((void**)&pw1l, d_w1l);

    dim3 t32(32,32);
    k_wconv<<<14851, 256>>>(rw1, rw2, g_w, th_w, ph_w, W_w, g_b, th_b, ph_b);
    k_xt  <<<dim3(128,8,4), t32>>>(x);
    k_mask<<<4, 1024>>>(mask);

    // fused QKG 1x1: N=768 over concat weights (g, theta, phi) -> d_qkg
    k_tmm<<<dim3(6,128),256,TM_SMEM_TOTAL>>>(pah, pal, pw1h, pw1l, pbc, pqkg,
                                             0, 0, 0, 1, 768);

    k_attn<<<dim3(256,4),256>>>();   // -> p-planes

    // W 1x1: p-planes -> wy fp32 + a-planes
    dim3 gg(2,128);
    k_tmm<<<gg,256,TM_SMEM_TOTAL>>>(pph, ppl, pw1h+3*65536, pw1l+3*65536, W_b, pwy,
                                    pah, pal, 0, 1, 256);

    for (int i=0;i<3;i++){
        k_tmm<<<gg,256,TM_SMEM_TOTAL>>>(pah, pal, pwbh + (size_t)(2*i)*9*65536,
                                        pwbl + (size_t)(2*i)*9*65536, rb1 + i*256,
                                        0, pth, ptl, pps, 9, 256);
        k_statf<<<4,256>>>();
        k_in_relu<<<8192,256>>>();
        k_tmm<<<gg,256,TM_SMEM_TOTAL>>>(pph, ppl, pwbh + (size_t)(2*i+1)*9*65536,
                                        pwbl + (size_t)(2*i+1)*9*65536, rb2 + i*256,
                                        0, pth, ptl, pps, 9, 256);
        k_statf<<<4,256>>>();
        k_in_add<<<8192,256>>>(pwy);
    }

    k_blend<<<dim3(128,8,4), t32>>>(x, z);
}

// round 13
// speedup vs baseline: 2.2289x; 2.2289x over previous
#include <cuda_runtime.h>
#include <cuda_fp16.h>
#include <math.h>
#include <stdint.h>

#define Bn 4
#define Cc 256
#define Nn 4096
#define Mm (Bn*Nn)   // 16384

// ---------------- helpers ----------------
__device__ __forceinline__ uint32_t smem_u32(const void* p){
    uint32_t a;
    asm("{ .reg .u64 t; cvta.to.shared.u64 t, %1; cvt.u32.u64 %0, t; }" : "=r"(a) : "l"(p));
    return a;
}
__device__ __forceinline__ int refl(int i, int n){ return i<0 ? -i : (i>=n ? 2*n-2-i : i); }

__device__ __forceinline__ void cpasync16(uint32_t dst, const void* src){
    asm volatile("cp.async.cg.shared.global [%0], [%1], 16;" :: "r"(dst), "l"(src) : "memory");
}
__device__ __forceinline__ void ldsm4(uint32_t (&r)[4], uint32_t addr){
    asm volatile("ldmatrix.sync.aligned.m8n8.x4.shared.b16 {%0,%1,%2,%3}, [%4];"
        : "=r"(r[0]), "=r"(r[1]), "=r"(r[2]), "=r"(r[3]) : "r"(addr));
}
__device__ __forceinline__ void mma16816(float (&d)[4], const uint32_t (&a)[4], const uint32_t* b){
    asm volatile("mma.sync.aligned.m16n8k16.row.col.f32.f16.f16.f32 "
        "{%0,%1,%2,%3},{%4,%5,%6,%7},{%8,%9},{%0,%1,%2,%3};"
        : "+f"(d[0]), "+f"(d[1]), "+f"(d[2]), "+f"(d[3])
        : "r"(a[0]), "r"(a[1]), "r"(a[2]), "r"(a[3]), "r"(b[0]), "r"(b[1]));
}
__device__ __forceinline__ void split16(float v, __half &h, __half &l){
    h = __float2half(v);
    l = __float2half(v - __half2float(h));
}

// ---------------- scratch (device globals) ----------------
__device__ float d_q [Mm*Cc];
__device__ float d_kk[Mm*Cc];
__device__ float d_gg[Mm*Cc];
__device__ float d_wy[Mm*Cc];
__device__ __half d_ah[Mm*Cc];   // activation planes (conv/gemm input)
__device__ __half d_al[Mm*Cc];
__device__ __half d_ph[Mm*Cc];   // post-relu / attention-out planes
__device__ __half d_pl[Mm*Cc];
__device__ __half d_th[Mm*Cc];   // conv output planes (pre-IN)
__device__ __half d_tl[Mm*Cc];
__device__ __half d_wbh[6*9*Cc*Cc];
__device__ __half d_wbl[6*9*Cc*Cc];
__device__ __half d_w1h[4*Cc*Cc];
__device__ __half d_w1l[4*Cc*Cc];
__device__ float d_mk[Mm];
__device__ int   d_act[Mm];
__device__ int   d_cnt[Bn];
__device__ float d_psum[2*Bn*Cc];   // zero-init; k_statf re-zeros after use
__device__ float d_mean[Bn*Cc];
__device__ float d_rstd[Bn*Cc];

// ---------------- weight conversion fp32 -> fp16 hi/lo ----------------
__global__ void k_wconv(const float* __restrict__ rw1, const float* __restrict__ rw2,
                        const float* __restrict__ gw, const float* __restrict__ tw,
                        const float* __restrict__ pw, const float* __restrict__ Ww){
    int idx = blockIdx.x*256 + threadIdx.x;
    const int NC = 6*9*65536;
    if (idx < NC){
        int cv = idx / (9*65536);
        int rem = idx - cv*(9*65536);
        int tap = rem >> 16;
        int oc = rem & 65535;
        int o = oc >> 8, c = oc & 255;
        int i = cv >> 1;
        const float* rw = (cv & 1) ? rw2 : rw1;
        float v = rw[(((i*256 + o)*256 + c)*9) + tap];
        __half h, l; split16(v, h, l);
        d_wbh[idx] = h; d_wbl[idx] = l;
    } else if (idx < NC + 4*65536){
        int j = idx - NC;
        int mat = j >> 16;
        int oc = j & 65535;
        const float* src = (mat==0) ? gw : (mat==1) ? tw : (mat==2) ? pw : Ww;
        __half h, l; split16(src[oc], h, l);
        d_w1h[j] = h; d_w1l[j] = l;
    }
}

// ---------------- x: NCHW -> fp16 hi/lo [B,N,C] ----------------
__global__ void k_xt(const float* __restrict__ x){
    __shared__ float tile[32][33];
    int b = blockIdx.z; int n0 = blockIdx.x*32, c0 = blockIdx.y*32;
    int tx = threadIdx.x, ty = threadIdx.y;
    tile[ty][tx] = x[((size_t)(b*Cc) + c0+ty)*Nn + n0+tx];
    __syncthreads();
    size_t o = ((size_t)(b*Nn) + n0+ty)*Cc + c0+tx;
    __half h, l; split16(tile[tx][ty], h, l);
    d_ah[o] = h; d_al[o] = l;
}

// ---------------- mask + active-key compaction ----------------
__global__ void k_mask(const float* __restrict__ mask){
    int b = blockIdx.x, t = threadIdx.x;
    __shared__ int sc[1024];
    const float* mb = mask + b*32*32;
    int flag[4]; int cnt = 0;
    #pragma unroll
    for (int i=0;i<4;i++){
        int n = t*4+i; int h = n>>6, w = n&63;
        float fy = h*0.5f - 0.25f, fx = w*0.5f - 0.25f;
        int y0 = (int)floorf(fy), x0 = (int)floorf(fx);
        float wy1 = fy - (float)y0, wx1 = fx - (float)x0;
        int y0c = min(max(y0,0),31), y1c = min(max(y0+1,0),31);
        int x0c = min(max(x0,0),31), x1c = min(max(x0+1,0),31);
        float v = (mb[y0c*32+x0c]*(1.f-wx1) + mb[y0c*32+x1c]*wx1)*(1.f-wy1)
                + (mb[y1c*32+x0c]*(1.f-wx1) + mb[y1c*32+x1c]*wx1)*wy1;
        float mv = (v > 0.f) ? 1.f : v;
        float a = 1.f - mv;
        float tmp = 1.f - mb[(h>>1)*32 + (w>>1)];
        float m = a * tmp;
        d_mk[b*Nn + n] = m;
        flag[i] = (m > 0.5f) ? 1 : 0;
        cnt += flag[i];
    }
    sc[t] = cnt; __syncthreads();
    for (int s=1; s<1024; s<<=1){
        int v = (t >= s) ? sc[t-s] : 0;
        __syncthreads();
        sc[t] += v;
        __syncthreads();
    }
    int base = sc[t] - cnt;
    #pragma unroll
    for (int i=0;i<4;i++) if (flag[i]) d_act[b*Nn + (base++)] = t*4+i;
    if (t == 1023) d_cnt[b] = sc[1023];
}

// ================= warp-MMA fp16 hi/lo GEMM / 3x3-reflect-conv =================
// 3-term split: AhWh + AlWh + AhWl (AlWl ~2^-24 dropped).
// 256 threads, 8 warps 4x2, warp tile 32x64.
// SMEM: 64B rows + XOR swizzle, plane 8KB, stage 32KB, 3 stages -> 2 CTAs/SM.
#define PLANE 8192
#define STAGE (4*PLANE)           // 32768
#define TM_SMEM_TOTAL (3*STAGE)   // 98304

__device__ __forceinline__ void tmm_load(uint32_t st,
    const __half* __restrict__ Ah, const __half* __restrict__ Al,
    const __half* __restrict__ Wh, const __half* __restrict__ Wl,
    int m0, int n0, int chunk, int ntaps, int t)
{
    int tap = chunk >> 3, k0 = (chunk & 7)*32;
    int dy = tap/3 - 1, dx = tap%3 - 1;
    #pragma unroll
    for (int it=0; it<2; it++){
        int e = t + it*256;
        int r = e >> 2, ch = e & 3;
        int slot = ch ^ ((r >> 1) & 3);
        uint32_t dst = st + r*64 + (slot << 4);
        int grow;
        if (ntaps > 1){
            int gg = m0 + r, b = gg >> 12, p = gg & 4095, h = p >> 6, w = p & 63;
            grow = (b << 12) + (refl(h+dy,64) << 6) + refl(w+dx,64);
        } else grow = m0 + r;
        size_t srcA = (size_t)grow*256 + k0 + ch*8;
        cpasync16(dst,         Ah + srcA);
        cpasync16(dst + PLANE, Al + srcA);
        size_t srcB = ((size_t)tap*256 + n0 + r)*256 + k0 + ch*8;
        cpasync16(dst + 2*PLANE, Wh + srcB);
        cpasync16(dst + 3*PLANE, Wl + srcB);
    }
}

__global__ void __launch_bounds__(256, 2)
k_tmm(const __half* __restrict__ Ah, const __half* __restrict__ Al,
      const __half* __restrict__ Wh, const __half* __restrict__ Wl,
      const float* __restrict__ bias, float* __restrict__ Cout,
      __half* __restrict__ Oh, __half* __restrict__ Ol,
      float* __restrict__ psum, int ntaps)
{
    extern __shared__ char smem[];
    uint32_t sb = smem_u32(smem);
    int t = threadIdx.x, lane = t & 31, wid = t >> 5;
    int warp_m = wid & 3, warp_n = wid >> 2;   // 4 x 2, warp tile 32x64
    int n0 = blockIdx.x * 128, m0 = blockIdx.y * 128;

    int S = ntaps * 8;
    float acc[2][8][4] = {};

    tmm_load(sb,         Ah, Al, Wh, Wl, m0, n0, 0, ntaps, t);
    asm volatile("cp.async.commit_group;" ::: "memory");
    if (S > 1){ tmm_load(sb + STAGE, Ah, Al, Wh, Wl, m0, n0, 1, ntaps, t);
                asm volatile("cp.async.commit_group;" ::: "memory"); }

    int rA  = warp_m*32 + (lane & 15);
    int hiA = lane >> 4;
    int sxA = (rA >> 1) & 3;
    uint32_t aRow = (uint32_t)rA * 64;
    int rB  = warp_n*64 + (lane & 7) + ((lane >> 4) << 3);
    int gB  = (lane >> 3) & 1;
    int sxB = (rB >> 1) & 3;
    uint32_t bRow = (uint32_t)rB * 64;

    for (int i = 0; i < S; i++){
        int rem = S - 1 - i;
        if (rem >= 1) asm volatile("cp.async.wait_group 1;" ::: "memory");
        else          asm volatile("cp.async.wait_group 0;" ::: "memory");
        __syncthreads();
        if (i + 2 < S){
            tmm_load(sb + (uint32_t)((i+2)%3)*STAGE, Ah, Al, Wh, Wl, m0, n0, i+2, ntaps, t);
            asm volatile("cp.async.commit_group;" ::: "memory");
        }
        uint32_t st = sb + (uint32_t)(i%3)*STAGE;
        #pragma unroll
        for (int kk = 0; kk < 2; kk++){
            uint32_t aAddr = st + aRow + ((uint32_t)(((2*kk) + hiA) ^ sxA) << 4);
            uint32_t aH[2][4], aL[2][4];
            ldsm4(aH[0], aAddr);
            ldsm4(aH[1], aAddr + 16*64);
            ldsm4(aL[0], aAddr + PLANE);
            ldsm4(aL[1], aAddr + PLANE + 16*64);
            #pragma unroll
            for (int ng = 0; ng < 2; ng++){
                uint32_t bAddr = st + 2*PLANE + bRow + (uint32_t)(ng*32*64)
                               + ((uint32_t)(((2*kk) + gB) ^ sxB) << 4);
                uint32_t bH[8], bL[8];
                ldsm4(*(uint32_t(*)[4])&bH[0], bAddr);
                ldsm4(*(uint32_t(*)[4])&bH[4], bAddr + 16*64);
                ldsm4(*(uint32_t(*)[4])&bL[0], bAddr + PLANE);
                ldsm4(*(uint32_t(*)[4])&bL[4], bAddr + PLANE + 16*64);
                #pragma unroll
                for (int j = 0; j < 4; j++){
                    int nt = ng*4 + j;
                    #pragma unroll
                    for (int mt = 0; mt < 2; mt++)
                        mma16816(acc[mt][nt], aH[mt], &bH[2*j]);
                }
                #pragma unroll
                for (int j = 0; j < 4; j++){
                    int nt = ng*4 + j;
                    #pragma unroll
                    for (int mt = 0; mt < 2; mt++)
                        mma16816(acc[mt][nt], aH[mt], &bL[2*j]);
                }
                #pragma unroll
                for (int j = 0; j < 4; j++){
                    int nt = ng*4 + j;
                    #pragma unroll
                    for (int mt = 0; mt < 2; mt++)
                        mma16816(acc[mt][nt], aL[mt], &bH[2*j]);
                }
            }
        }
    }

    // ---- epilogue (+ fused IN stats) ----
    int rbase = m0 + warp_m*32;
    int nb = n0 + warp_n*64;
    int rr = lane >> 2, c2 = 2*(lane & 3);
    float cs[16] = {}, cs2[16] = {};
    #pragma unroll
    for (int mt = 0; mt < 2; mt++){
        #pragma unroll
        for (int nt = 0; nt < 8; nt++){
            int row = rbase + mt*16 + rr;
            int col = nb + nt*8 + c2;
            float b0 = bias[col], b1 = bias[col+1];
            float v00 = acc[mt][nt][0] + b0, v01 = acc[mt][nt][1] + b1;
            float v10 = acc[mt][nt][2] + b0, v11 = acc[mt][nt][3] + b1;
            if (Cout){
                float2 p0; p0.x = v00; p0.y = v01;
                float2 p1; p1.x = v10; p1.y = v11;
                *(float2*)&Cout[(size_t)row*256 + col] = p0;
                *(float2*)&Cout[(size_t)(row+8)*256 + col] = p1;
            }
            if (Oh){
                __half h00, l00, h01, l01, h10, l10, h11, l11;
                split16(v00, h00, l00); split16(v01, h01, l01);
                split16(v10, h10, l10); split16(v11, h11, l11);
                *(__half2*)&Oh[(size_t)row*256 + col]     = __halves2half2(h00, h01);
                *(__half2*)&Ol[(size_t)row*256 + col]     = __halves2half2(l00, l01);
                *(__half2*)&Oh[(size_t)(row+8)*256 + col] = __halves2half2(h10, h11);
                *(__half2*)&Ol[(size_t)(row+8)*256 + col] = __halves2half2(l10, l11);
            }
            cs [nt*2]   += v00 + v10;
            cs [nt*2+1] += v01 + v11;
            cs2[nt*2]   += v00*v00 + v10*v10;
            cs2[nt*2+1] += v01*v01 + v11*v11;
        }
    }
    if (psum){
        #pragma unroll
        for (int o = 4; o <= 16; o <<= 1){
            #pragma unroll
            for (int j = 0; j < 16; j++){
                cs[j]  += __shfl_xor_sync(0xffffffffu, cs[j],  o);
                cs2[j] += __shfl_xor_sync(0xffffffffu, cs2[j], o);
            }
        }
        if (lane < 4){
            int b = m0 >> 12;
            #pragma unroll
            for (int nt = 0; nt < 8; nt++){
                int col = nb + nt*8 + 2*lane;
                atomicAdd(&psum[b*256 + col],          cs [2*nt]);
                atomicAdd(&psum[b*256 + col + 1],      cs [2*nt+1]);
                atomicAdd(&psum[1024 + b*256 + col],   cs2[2*nt]);
                atomicAdd(&psum[1024 + b*256 + col+1], cs2[2*nt+1]);
            }
        }
    }
}

// ---------------- masked-softmax attention over compacted keys ----------------
// QK: float4 reads (rows padded to 260 floats). PV: conflict-free scalar mapping.
// __expf (MUFU) replaces library expf.
__global__ void __launch_bounds__(256) k_attn(){
    int b = blockIdx.y; int q0 = blockIdx.x * 16;
    __shared__ float Qs[16][260];
    __shared__ float Ks[16][260];
    __shared__ float Gs[16][260];
    __shared__ float Ss[16][17];
    int t = threadIdx.x;
    for (int i4 = t; i4 < 16*64; i4 += 256){
        int r = i4 >> 6, c4 = (i4 & 63) * 4;
        *(float4*)&Qs[r][c4] = *(const float4*)&d_q[((size_t)(b*Nn) + q0 + r)*256 + c4];
    }
    int cnt = d_cnt[b];
    int q = t >> 4, lane = t & 15;
    float yacc[16];
    #pragma unroll
    for (int i=0;i<16;i++) yacc[i] = 0.f;
    float rmax = -1e30f, rsum = 0.f;
    __syncthreads();
    for (int j0=0; j0<cnt; j0+=16){
        int jn = min(16, cnt - j0);
        for (int i4 = t; i4 < jn*64; i4 += 256){
            int r = i4 >> 6, c4 = (i4 & 63) * 4;
            int src = d_act[b*Nn + j0 + r];
            *(float4*)&Ks[r][c4] = *(const float4*)&d_kk[((size_t)(b*Nn) + src)*256 + c4];
            *(float4*)&Gs[r][c4] = *(const float4*)&d_gg[((size_t)(b*Nn) + src)*256 + c4];
        }
        __syncthreads();
        float s = -1e30f;
        if (lane < jn){
            s = 0.f;
            #pragma unroll 4
            for (int c4 = 0; c4 < 64; c4++){
                float4 qv = *(const float4*)&Qs[q][c4*4];
                float4 kv = *(const float4*)&Ks[lane][c4*4];
                s += qv.x*kv.x + qv.y*kv.y + qv.z*kv.z + qv.w*kv.w;
            }
        }
        Ss[q][lane] = s;
        __syncthreads();
        float cmax = rmax;
        for (int j=0;j<jn;j++) cmax = fmaxf(cmax, Ss[q][j]);
        float scale = __expf(rmax - cmax);
        rsum *= scale;
        #pragma unroll
        for (int i=0;i<16;i++) yacc[i] *= scale;
        for (int j=0;j<jn;j++){
            float pj = __expf(Ss[q][j] - cmax);
            rsum += pj;
            #pragma unroll
            for (int i=0;i<16;i++) yacc[i] += pj * Gs[j][lane + i*16];
        }
        rmax = cmax;
        __syncthreads();
    }
    float inv = (rsum > 0.f) ? (1.f/rsum) : 0.f;
    #pragma unroll
    for (int i=0;i<16;i++){
        float v = yacc[i]*inv;
        size_t o = ((size_t)(b*Nn) + q0 + q)*256 + lane + i*16;
        __half h, l; split16(v, h, l);
        d_ph[o] = h; d_pl[o] = l;
    }
}

// ---------------- instance-norm finalize (reads+zeros psum) ----------------
__global__ void k_statf(){
    int b = blockIdx.x, c = threadIdx.x;
    float s  = d_psum[b*256 + c];
    float s2 = d_psum[1024 + b*256 + c];
    float mu = s * (1.f/4096.f);
    float var = s2 * (1.f/4096.f) - mu*mu;
    d_mean[b*256+c] = mu;
    d_rstd[b*256+c] = rsqrtf(var + 1e-5f);
    d_psum[b*256 + c] = 0.f;
    d_psum[1024 + b*256 + c] = 0.f;
}

// relu(IN(t-planes)) -> p-planes   (2 elems/thread)
__global__ void k_in_relu(){
    int i2 = blockIdx.x*256 + threadIdx.x;
    int base = i2*2;
    int c = base & 255; int b = base >> 20;
    __half2 h2 = *(const __half2*)&d_th[base];
    __half2 l2 = *(const __half2*)&d_tl[base];
    float v0 = __half2float(h2.x) + __half2float(l2.x);
    float v1 = __half2float(h2.y) + __half2float(l2.y);
    v0 = fmaxf((v0 - d_mean[b*256+c])   * d_rstd[b*256+c],   0.f);
    v1 = fmaxf((v1 - d_mean[b*256+c+1]) * d_rstd[b*256+c+1], 0.f);
    __half h0, l0, h1, l1; split16(v0, h0, l0); split16(v1, h1, l1);
    *(__half2*)&d_ph[base] = __halves2half2(h0, h1);
    *(__half2*)&d_pl[base] = __halves2half2(l0, l1);
}
// wy += IN(t-planes); write new a-planes
__global__ void k_in_add(float* __restrict__ io){
    int i2 = blockIdx.x*256 + threadIdx.x;
    int base = i2*2;
    int c = base & 255; int b = base >> 20;
    __half2 h2 = *(const __half2*)&d_th[base];
    __half2 l2 = *(const __half2*)&d_tl[base];
    float v0 = __half2float(h2.x) + __half2float(l2.x);
    float v1 = __half2float(h2.y) + __half2float(l2.y);
    float2 w = *(float2*)&io[base];
    w.x += (v0 - d_mean[b*256+c])   * d_rstd[b*256+c];
    w.y += (v1 - d_mean[b*256+c+1]) * d_rstd[b*256+c+1];
    *(float2*)&io[base] = w;
    __half h0, l0, h1, l1; split16(w.x, h0, l0); split16(w.y, h1, l1);
    *(__half2*)&d_ah[base] = __halves2half2(h0, h1);
    *(__half2*)&d_al[base] = __halves2half2(l0, l1);
}

// ---------------- final blend + NHWC->NCHW ----------------
__global__ void k_blend(const float* __restrict__ x, float* __restrict__ z){
    __shared__ float tile[32][33];
    int b = blockIdx.z; int n0 = blockIdx.x*32, c0 = blockIdx.y*32;
    int tx = threadIdx.x, ty = threadIdx.y;
    tile[ty][tx] = d_wy[((size_t)(b*Nn) + n0+ty)*256 + c0+tx];
    __syncthreads();
    int n = n0 + tx, c = c0 + ty;
    float m = d_mk[b*Nn + n];
    size_t idx = ((size_t)(b*Cc + c))*Nn + n;
    z[idx] = m * x[idx] + (1.f - m) * tile[tx][ty];
}

// ---------------- launch ----------------
extern "C" void kernel_launch(void* const* d_in, const int* in_sizes, int n_in,
                              void* d_out, int out_size) {
    (void)in_sizes; (void)n_in; (void)out_size;
    const float* x    = (const float*)d_in[0];
    const float* mask = (const float*)d_in[1];
    const float* g_w  = (const float*)d_in[2];
    const float* g_b  = (const float*)d_in[3];
    const float* th_w = (const float*)d_in[4];
    const float* th_b = (const float*)d_in[5];
    const float* ph_w = (const float*)d_in[6];
    const float* ph_b = (const float*)d_in[7];
    const float* W_w  = (const float*)d_in[8];
    const float* W_b  = (const float*)d_in[9];
    const float* rw1  = (const float*)d_in[10];
    const float* rb1  = (const float*)d_in[11];
    const float* rw2  = (const float*)d_in[12];
    const float* rb2  = (const float*)d_in[13];
    float* z = (float*)d_out;

    cudaFuncSetAttribute(k_tmm, cudaFuncAttributeMaxDynamicSharedMemorySize, TM_SMEM_TOTAL);

    float *pq, *pk, *pg, *pwy, *pps;
    __half *pah, *pal, *pph, *ppl, *pth, *ptl, *pwbh, *pwbl, *pw1h, *pw1l;
    cudaGetSymbolAddress((void**)&pq,  d_q);
    cudaGetSymbolAddress((void**)&pk,  d_kk);
    cudaGetSymbolAddress((void**)&pg,  d_gg);
    cudaGetSymbolAddress((void**)&pwy, d_wy);
    cudaGetSymbolAddress((void**)&pps, d_psum);
    cudaGetSymbolAddress((void**)&pah, d_ah);
    cudaGetSymbolAddress((void**)&pal, d_al);
    cudaGetSymbolAddress((void**)&pph, d_ph);
    cudaGetSymbolAddress((void**)&ppl, d_pl);
    cudaGetSymbolAddress((void**)&pth, d_th);
    cudaGetSymbolAddress((void**)&ptl, d_tl);
    cudaGetSymbolAddress((void**)&pwbh, d_wbh);
    cudaGetSymbolAddress((void**)&pwbl, d_wbl);
    cudaGetSymbolAddress((void**)&pw1h, d_w1h);
    cudaGetSymbolAddress((void**)&pw1l, d_w1l);

    dim3 t32(32,32);
    k_wconv<<<14848, 256>>>(rw1, rw2, g_w, th_w, ph_w, W_w);
    k_xt  <<<dim3(128,8,4), t32>>>(x);
    k_mask<<<4, 1024>>>(mask);

    dim3 gg(2,128);
    k_tmm<<<gg,256,TM_SMEM_TOTAL>>>(pah, pal, pw1h+1*65536, pw1l+1*65536, th_b, pq, 0, 0, 0, 1);
    k_tmm<<<gg,256,TM_SMEM_TOTAL>>>(pah, pal, pw1h+2*65536, pw1l+2*65536, ph_b, pk, 0, 0, 0, 1);
    k_tmm<<<gg,256,TM_SMEM_TOTAL>>>(pah, pal, pw1h+0*65536, pw1l+0*65536, g_b,  pg, 0, 0, 0, 1);

    k_attn<<<dim3(256,4),256>>>();   // -> p-planes

    // W 1x1: p-planes -> wy fp32 + a-planes
    k_tmm<<<gg,256,TM_SMEM_TOTAL>>>(pph, ppl, pw1h+3*65536, pw1l+3*65536, W_b, pwy, pah, pal, 0, 1);

    for (int i=0;i<3;i++){
        k_tmm<<<gg,256,TM_SMEM_TOTAL>>>(pah, pal, pwbh + (size_t)(2*i)*9*65536,
                                        pwbl + (size_t)(2*i)*9*65536, rb1 + i*256,
                                        0, pth, ptl, pps, 9);
        k_statf<<<4,256>>>();
        k_in_relu<<<8192,256>>>();
        k_tmm<<<gg,256,TM_SMEM_TOTAL>>>(pph, ppl, pwbh + (size_t)(2*i+1)*9*65536,
                                        pwbl + (size_t)(2*i+1)*9*65536, rb2 + i*256,
                                        0, pth, ptl, pps, 9);
        k_statf<<<4,256>>>();
        k_in_add<<<8192,256>>>(pwy);
    }

    k_blend<<<dim3(128,8,4), t32>>>(x, z);
}

// round 14
// speedup vs baseline: 2.6508x; 1.1893x over previous
#include <cuda_runtime.h>
#include <cuda_fp16.h>
#include <math.h>
#include <stdint.h>

#define Bn 4
#define Cc 256
#define Nn 4096
#define Mm (Bn*Nn)   // 16384

// ---------------- helpers ----------------
__device__ __forceinline__ uint32_t smem_u32(const void* p){
    uint32_t a;
    asm("{ .reg .u64 t; cvta.to.shared.u64 t, %1; cvt.u32.u64 %0, t; }" : "=r"(a) : "l"(p));
    return a;
}
__device__ __forceinline__ int refl(int i, int n){ return i<0 ? -i : (i>=n ? 2*n-2-i : i); }

__device__ __forceinline__ void cpasync16(uint32_t dst, const void* src){
    asm volatile("cp.async.cg.shared.global [%0], [%1], 16;" :: "r"(dst), "l"(src) : "memory");
}
__device__ __forceinline__ void ldsm4(uint32_t (&r)[4], uint32_t addr){
    asm volatile("ldmatrix.sync.aligned.m8n8.x4.shared.b16 {%0,%1,%2,%3}, [%4];"
        : "=r"(r[0]), "=r"(r[1]), "=r"(r[2]), "=r"(r[3]) : "r"(addr));
}
__device__ __forceinline__ void mma16816(float (&d)[4], const uint32_t (&a)[4], const uint32_t* b){
    asm volatile("mma.sync.aligned.m16n8k16.row.col.f32.f16.f16.f32 "
        "{%0,%1,%2,%3},{%4,%5,%6,%7},{%8,%9},{%0,%1,%2,%3};"
        : "+f"(d[0]), "+f"(d[1]), "+f"(d[2]), "+f"(d[3])
        : "r"(a[0]), "r"(a[1]), "r"(a[2]), "r"(a[3]), "r"(b[0]), "r"(b[1]));
}
__device__ __forceinline__ void split16(float v, __half &h, __half &l){
    h = __float2half(v);
    l = __float2half(v - __half2float(h));
}

// ---------------- scratch (device globals) ----------------
__device__ float d_q [Mm*Cc];
__device__ float d_kk[Mm*Cc];
__device__ float d_gg[Mm*Cc];
__device__ float d_wy[Mm*Cc];
__device__ __half d_ah[Mm*Cc];   // activation planes
__device__ __half d_al[Mm*Cc];
__device__ __half d_ph[Mm*Cc];   // post-relu / attention-out planes
__device__ __half d_pl[Mm*Cc];
__device__ __half d_th[Mm*Cc];   // conv output planes (pre-IN)
__device__ __half d_tl[Mm*Cc];
__device__ __half d_wbh[6*9*Cc*Cc];
__device__ __half d_wbl[6*9*Cc*Cc];
__device__ __half d_w1h[4*Cc*Cc];
__device__ __half d_w1l[4*Cc*Cc];
__device__ float d_mk[Mm];
__device__ int   d_act[Mm];
__device__ int   d_cnt[Bn];
__device__ float d_psum[2*Bn*Cc];   // zero-init; k_statf re-zeros after use
__device__ float d_mean[Bn*Cc];
__device__ float d_rstd[Bn*Cc];

// ---------------- weight conversion fp32 -> fp16 hi/lo ----------------
__global__ void k_wconv(const float* __restrict__ rw1, const float* __restrict__ rw2,
                        const float* __restrict__ gw, const float* __restrict__ tw,
                        const float* __restrict__ pw, const float* __restrict__ Ww){
    int idx = blockIdx.x*256 + threadIdx.x;
    const int NC = 6*9*65536;
    if (idx < NC){
        int cv = idx / (9*65536);
        int rem = idx - cv*(9*65536);
        int tap = rem >> 16;
        int oc = rem & 65535;
        int o = oc >> 8, c = oc & 255;
        int i = cv >> 1;
        const float* rw = (cv & 1) ? rw2 : rw1;
        float v = rw[(((i*256 + o)*256 + c)*9) + tap];
        __half h, l; split16(v, h, l);
        d_wbh[idx] = h; d_wbl[idx] = l;
    } else if (idx < NC + 4*65536){
        int j = idx - NC;
        int mat = j >> 16;
        int oc = j & 65535;
        const float* src = (mat==0) ? gw : (mat==1) ? tw : (mat==2) ? pw : Ww;
        __half h, l; split16(src[oc], h, l);
        d_w1h[j] = h; d_w1l[j] = l;
    }
}

// ---------------- x: NCHW -> fp16 hi/lo [B,N,C] ----------------
__global__ void k_xt(const float* __restrict__ x){
    __shared__ float tile[32][33];
    int b = blockIdx.z; int n0 = blockIdx.x*32, c0 = blockIdx.y*32;
    int tx = threadIdx.x, ty = threadIdx.y;
    tile[ty][tx] = x[((size_t)(b*Cc) + c0+ty)*Nn + n0+tx];
    __syncthreads();
    size_t o = ((size_t)(b*Nn) + n0+ty)*Cc + c0+tx;
    __half h, l; split16(tile[tx][ty], h, l);
    d_ah[o] = h; d_al[o] = l;
}

// ---------------- mask + active-key compaction ----------------
__global__ void k_mask(const float* __restrict__ mask){
    int b = blockIdx.x, t = threadIdx.x;
    __shared__ int sc[1024];
    const float* mb = mask + b*32*32;
    int flag[4]; int cnt = 0;
    #pragma unroll
    for (int i=0;i<4;i++){
        int n = t*4+i; int h = n>>6, w = n&63;
        float fy = h*0.5f - 0.25f, fx = w*0.5f - 0.25f;
        int y0 = (int)floorf(fy), x0 = (int)floorf(fx);
        float wy1 = fy - (float)y0, wx1 = fx - (float)x0;
        int y0c = min(max(y0,0),31), y1c = min(max(y0+1,0),31);
        int x0c = min(max(x0,0),31), x1c = min(max(x0+1,0),31);
        float v = (mb[y0c*32+x0c]*(1.f-wx1) + mb[y0c*32+x1c]*wx1)*(1.f-wy1)
                + (mb[y1c*32+x0c]*(1.f-wx1) + mb[y1c*32+x1c]*wx1)*wy1;
        float mv = (v > 0.f) ? 1.f : v;
        float a = 1.f - mv;
        float tmp = 1.f - mb[(h>>1)*32 + (w>>1)];
        float m = a * tmp;
        d_mk[b*Nn + n] = m;
        flag[i] = (m > 0.5f) ? 1 : 0;
        cnt += flag[i];
    }
    sc[t] = cnt; __syncthreads();
    for (int s=1; s<1024; s<<=1){
        int v = (t >= s) ? sc[t-s] : 0;
        __syncthreads();
        sc[t] += v;
        __syncthreads();
    }
    int base = sc[t] - cnt;
    #pragma unroll
    for (int i=0;i<4;i++) if (flag[i]) d_act[b*Nn + (base++)] = t*4+i;
    if (t == 1023) d_cnt[b] = sc[1023];
}

#define PLANE 8192
// ================= 3-term 1x1 GEMM kernel (unchanged, proven) =================
#define STAGE (4*PLANE)           // 32768
#define TM_SMEM_TOTAL (3*STAGE)   // 98304

__device__ __forceinline__ void tmm_load(uint32_t st,
    const __half* __restrict__ Ah, const __half* __restrict__ Al,
    const __half* __restrict__ Wh, const __half* __restrict__ Wl,
    int m0, int n0, int chunk, int t)
{
    int k0 = (chunk & 7)*32;
    #pragma unroll
    for (int it=0; it<2; it++){
        int e = t + it*256;
        int r = e >> 2, ch = e & 3;
        int slot = ch ^ ((r >> 1) & 3);
        uint32_t dst = st + r*64 + (slot << 4);
        size_t srcA = (size_t)(m0 + r)*256 + k0 + ch*8;
        cpasync16(dst,         Ah + srcA);
        cpasync16(dst + PLANE, Al + srcA);
        size_t srcB = ((size_t)(n0 + r))*256 + k0 + ch*8;
        cpasync16(dst + 2*PLANE, Wh + srcB);
        cpasync16(dst + 3*PLANE, Wl + srcB);
    }
}

__global__ void __launch_bounds__(256, 2)
k_tmm(const __half* __restrict__ Ah, const __half* __restrict__ Al,
      const __half* __restrict__ Wh, const __half* __restrict__ Wl,
      const float* __restrict__ bias, float* __restrict__ Cout,
      __half* __restrict__ Oh, __half* __restrict__ Ol)
{
    extern __shared__ char smem[];
    uint32_t sb = smem_u32(smem);
    int t = threadIdx.x, lane = t & 31, wid = t >> 5;
    int warp_m = wid & 3, warp_n = wid >> 2;
    int n0 = blockIdx.x * 128, m0 = blockIdx.y * 128;

    const int S = 8;
    float acc[2][8][4] = {};

    tmm_load(sb,         Ah, Al, Wh, Wl, m0, n0, 0, t);
    asm volatile("cp.async.commit_group;" ::: "memory");
    tmm_load(sb + STAGE, Ah, Al, Wh, Wl, m0, n0, 1, t);
    asm volatile("cp.async.commit_group;" ::: "memory");

    int rA  = warp_m*32 + (lane & 15);
    int hiA = lane >> 4;
    int sxA = (rA >> 1) & 3;
    uint32_t aRow = (uint32_t)rA * 64;
    int rB  = warp_n*64 + (lane & 7) + ((lane >> 4) << 3);
    int gB  = (lane >> 3) & 1;
    int sxB = (rB >> 1) & 3;
    uint32_t bRow = (uint32_t)rB * 64;

    for (int i = 0; i < S; i++){
        int rem = S - 1 - i;
        if (rem >= 1) asm volatile("cp.async.wait_group 1;" ::: "memory");
        else          asm volatile("cp.async.wait_group 0;" ::: "memory");
        __syncthreads();
        if (i + 2 < S){
            tmm_load(sb + (uint32_t)((i+2)%3)*STAGE, Ah, Al, Wh, Wl, m0, n0, i+2, t);
            asm volatile("cp.async.commit_group;" ::: "memory");
        }
        uint32_t st = sb + (uint32_t)(i%3)*STAGE;
        #pragma unroll
        for (int kk = 0; kk < 2; kk++){
            uint32_t aAddr = st + aRow + ((uint32_t)(((2*kk) + hiA) ^ sxA) << 4);
            uint32_t aH[2][4], aL[2][4];
            ldsm4(aH[0], aAddr);
            ldsm4(aH[1], aAddr + 16*64);
            ldsm4(aL[0], aAddr + PLANE);
            ldsm4(aL[1], aAddr + PLANE + 16*64);
            #pragma unroll
            for (int ng = 0; ng < 2; ng++){
                uint32_t bAddr = st + 2*PLANE + bRow + (uint32_t)(ng*32*64)
                               + ((uint32_t)(((2*kk) + gB) ^ sxB) << 4);
                uint32_t bH[8], bL[8];
                ldsm4(*(uint32_t(*)[4])&bH[0], bAddr);
                ldsm4(*(uint32_t(*)[4])&bH[4], bAddr + 16*64);
                ldsm4(*(uint32_t(*)[4])&bL[0], bAddr + PLANE);
                ldsm4(*(uint32_t(*)[4])&bL[4], bAddr + PLANE + 16*64);
                #pragma unroll
                for (int j = 0; j < 4; j++){
                    int nt = ng*4 + j;
                    #pragma unroll
                    for (int mt = 0; mt < 2; mt++)
                        mma16816(acc[mt][nt], aH[mt], &bH[2*j]);
                }
                #pragma unroll
                for (int j = 0; j < 4; j++){
                    int nt = ng*4 + j;
                    #pragma unroll
                    for (int mt = 0; mt < 2; mt++)
                        mma16816(acc[mt][nt], aH[mt], &bL[2*j]);
                }
                #pragma unroll
                for (int j = 0; j < 4; j++){
                    int nt = ng*4 + j;
                    #pragma unroll
                    for (int mt = 0; mt < 2; mt++)
                        mma16816(acc[mt][nt], aL[mt], &bH[2*j]);
                }
            }
        }
    }

    int rbase = m0 + warp_m*32;
    int nb = n0 + warp_n*64;
    int rr = lane >> 2, c2 = 2*(lane & 3);
    #pragma unroll
    for (int mt = 0; mt < 2; mt++){
        #pragma unroll
        for (int nt = 0; nt < 8; nt++){
            int row = rbase + mt*16 + rr;
            int col = nb + nt*8 + c2;
            float b0 = bias[col], b1 = bias[col+1];
            float v00 = acc[mt][nt][0] + b0, v01 = acc[mt][nt][1] + b1;
            float v10 = acc[mt][nt][2] + b0, v11 = acc[mt][nt][3] + b1;
            if (Cout){
                float2 p0; p0.x = v00; p0.y = v01;
                float2 p1; p1.x = v10; p1.y = v11;
                *(float2*)&Cout[(size_t)row*256 + col] = p0;
                *(float2*)&Cout[(size_t)(row+8)*256 + col] = p1;
            }
            if (Oh){
                __half h00, l00, h01, l01, h10, l10, h11, l11;
                split16(v00, h00, l00); split16(v01, h01, l01);
                split16(v10, h10, l10); split16(v11, h11, l11);
                *(__half2*)&Oh[(size_t)row*256 + col]     = __halves2half2(h00, h01);
                *(__half2*)&Ol[(size_t)row*256 + col]     = __halves2half2(l00, l01);
                *(__half2*)&Oh[(size_t)(row+8)*256 + col] = __halves2half2(h10, h11);
                *(__half2*)&Ol[(size_t)(row+8)*256 + col] = __halves2half2(l10, l11);
            }
        }
    }
}

// ================= 2-term conv kernel: D = Ah @ (Wh + Wl) =================
// 3 planes per stage (A, Bh, Bl) = 24KB, 4 stages, ONE barrier per chunk pair.
#define STAGE3 (3*PLANE)            // 24576
#define TC_SMEM_TOTAL (4*STAGE3)    // 98304

__device__ __forceinline__ void tmmc_load(uint32_t st,
    const __half* __restrict__ Ah,
    const __half* __restrict__ Wh, const __half* __restrict__ Wl,
    int m0, int n0, int chunk, int t)
{
    int tap = chunk >> 3, k0 = (chunk & 7)*32;
    int dy = tap/3 - 1, dx = tap%3 - 1;
    #pragma unroll
    for (int it=0; it<2; it++){
        int e = t + it*256;
        int r = e >> 2, ch = e & 3;
        int slot = ch ^ ((r >> 1) & 3);
        uint32_t dst = st + r*64 + (slot << 4);
        int gg = m0 + r, b = gg >> 12, p = gg & 4095, h = p >> 6, w = p & 63;
        int grow = (b << 12) + (refl(h+dy,64) << 6) + refl(w+dx,64);
        cpasync16(dst, Ah + (size_t)grow*256 + k0 + ch*8);
        size_t srcB = ((size_t)tap*256 + n0 + r)*256 + k0 + ch*8;
        cpasync16(dst + PLANE,   Wh + srcB);
        cpasync16(dst + 2*PLANE, Wl + srcB);
    }
}

__global__ void __launch_bounds__(256, 2)
k_tmmc(const __half* __restrict__ Ah,
       const __half* __restrict__ Wh, const __half* __restrict__ Wl,
       const float* __restrict__ bias,
       __half* __restrict__ Oh, __half* __restrict__ Ol,
       float* __restrict__ psum)
{
    extern __shared__ char smem[];
    uint32_t sb = smem_u32(smem);
    int t = threadIdx.x, lane = t & 31, wid = t >> 5;
    int warp_m = wid & 3, warp_n = wid >> 2;
    int n0 = blockIdx.x * 128, m0 = blockIdx.y * 128;

    const int S = 72;
    float acc[2][8][4] = {};

    // prologue: chunks 0,1 into stages 0,1 (one group)
    tmmc_load(sb,          Ah, Wh, Wl, m0, n0, 0, t);
    tmmc_load(sb + STAGE3, Ah, Wh, Wl, m0, n0, 1, t);
    asm volatile("cp.async.commit_group;" ::: "memory");

    int rA  = warp_m*32 + (lane & 15);
    int hiA = lane >> 4;
    int sxA = (rA >> 1) & 3;
    uint32_t aRow = (uint32_t)rA * 64;
    int rB  = warp_n*64 + (lane & 7) + ((lane >> 4) << 3);
    int gB  = (lane >> 3) & 1;
    int sxB = (rB >> 1) & 3;
    uint32_t bRow = (uint32_t)rB * 64;

    for (int p = 0; p < S/2; p++){
        // all outstanding loads (chunks 2p,2p+1) complete, then block-wide visibility
        asm volatile("cp.async.wait_group 0;" ::: "memory");
        __syncthreads();
        // prefetch next pair into stages (2p+2)%4,(2p+3)%4 (their prior readers
        // finished pair p-1; guaranteed by the barrier above)
        if (2*p + 2 < S){
            tmmc_load(sb + (uint32_t)((2*p+2)&3)*STAGE3, Ah, Wh, Wl, m0, n0, 2*p+2, t);
            tmmc_load(sb + (uint32_t)((2*p+3)&3)*STAGE3, Ah, Wh, Wl, m0, n0, 2*p+3, t);
            asm volatile("cp.async.commit_group;" ::: "memory");
        }
        #pragma unroll
        for (int q = 0; q < 2; q++){
            uint32_t st = sb + (uint32_t)((2*p+q)&3)*STAGE3;
            #pragma unroll
            for (int kk = 0; kk < 2; kk++){
                uint32_t aAddr = st + aRow + ((uint32_t)(((2*kk) + hiA) ^ sxA) << 4);
                uint32_t aH[2][4];
                ldsm4(aH[0], aAddr);
                ldsm4(aH[1], aAddr + 16*64);
                #pragma unroll
                for (int ng = 0; ng < 2; ng++){
                    uint32_t bAddr = st + PLANE + bRow + (uint32_t)(ng*32*64)
                                   + ((uint32_t)(((2*kk) + gB) ^ sxB) << 4);
                    uint32_t bH[8], bL[8];
                    ldsm4(*(uint32_t(*)[4])&bH[0], bAddr);
                    ldsm4(*(uint32_t(*)[4])&bH[4], bAddr + 16*64);
                    ldsm4(*(uint32_t(*)[4])&bL[0], bAddr + PLANE);
                    ldsm4(*(uint32_t(*)[4])&bL[4], bAddr + PLANE + 16*64);
                    #pragma unroll
                    for (int j = 0; j < 4; j++){
                        int nt = ng*4 + j;
                        #pragma unroll
                        for (int mt = 0; mt < 2; mt++)
                            mma16816(acc[mt][nt], aH[mt], &bH[2*j]);
                    }
                    #pragma unroll
                    for (int j = 0; j < 4; j++){
                        int nt = ng*4 + j;
                        #pragma unroll
                        for (int mt = 0; mt < 2; mt++)
                            mma16816(acc[mt][nt], aH[mt], &bL[2*j]);
                    }
                }
            }
        }
    }

    // ---- epilogue: planes + fused IN stats ----
    int rbase = m0 + warp_m*32;
    int nb = n0 + warp_n*64;
    int rr = lane >> 2, c2 = 2*(lane & 3);
    float cs[16] = {}, cs2[16] = {};
    #pragma unroll
    for (int mt = 0; mt < 2; mt++){
        #pragma unroll
        for (int nt = 0; nt < 8; nt++){
            int row = rbase + mt*16 + rr;
            int col = nb + nt*8 + c2;
            float b0 = bias[col], b1 = bias[col+1];
            float v00 = acc[mt][nt][0] + b0, v01 = acc[mt][nt][1] + b1;
            float v10 = acc[mt][nt][2] + b0, v11 = acc[mt][nt][3] + b1;
            __half h00, l00, h01, l01, h10, l10, h11, l11;
            split16(v00, h00, l00); split16(v01, h01, l01);
            split16(v10, h10, l10); split16(v11, h11, l11);
            *(__half2*)&Oh[(size_t)row*256 + col]     = __halves2half2(h00, h01);
            *(__half2*)&Ol[(size_t)row*256 + col]     = __halves2half2(l00, l01);
            *(__half2*)&Oh[(size_t)(row+8)*256 + col] = __halves2half2(h10, h11);
            *(__half2*)&Ol[(size_t)(row+8)*256 + col] = __halves2half2(l10, l11);
            cs [nt*2]   += v00 + v10;
            cs [nt*2+1] += v01 + v11;
            cs2[nt*2]   += v00*v00 + v10*v10;
            cs2[nt*2+1] += v01*v01 + v11*v11;
        }
    }
    #pragma unroll
    for (int o = 4; o <= 16; o <<= 1){
        #pragma unroll
        for (int j = 0; j < 16; j++){
            cs[j]  += __shfl_xor_sync(0xffffffffu, cs[j],  o);
            cs2[j] += __shfl_xor_sync(0xffffffffu, cs2[j], o);
        }
    }
    if (lane < 4){
        int b = m0 >> 12;
        #pragma unroll
        for (int nt = 0; nt < 8; nt++){
            int col = nb + nt*8 + 2*lane;
            atomicAdd(&psum[b*256 + col],          cs [2*nt]);
            atomicAdd(&psum[b*256 + col + 1],      cs [2*nt+1]);
            atomicAdd(&psum[1024 + b*256 + col],   cs2[2*nt]);
            atomicAdd(&psum[1024 + b*256 + col+1], cs2[2*nt+1]);
        }
    }
}

// ---------------- masked-softmax attention over compacted keys ----------------
__global__ void __launch_bounds__(256) k_attn(){
    int b = blockIdx.y; int q0 = blockIdx.x * 16;
    __shared__ float Qs[16][260];
    __shared__ float Ks[16][260];
    __shared__ float Gs[16][260];
    __shared__ float Ss[16][17];
    int t = threadIdx.x;
    for (int i4 = t; i4 < 16*64; i4 += 256){
        int r = i4 >> 6, c4 = (i4 & 63) * 4;
        *(float4*)&Qs[r][c4] = *(const float4*)&d_q[((size_t)(b*Nn) + q0 + r)*256 + c4];
    }
    int cnt = d_cnt[b];
    int q = t >> 4, lane = t & 15;
    float yacc[16];
    #pragma unroll
    for (int i=0;i<16;i++) yacc[i] = 0.f;
    float rmax = -1e30f, rsum = 0.f;
    __syncthreads();
    for (int j0=0; j0<cnt; j0+=16){
        int jn = min(16, cnt - j0);
        for (int i4 = t; i4 < jn*64; i4 += 256){
            int r = i4 >> 6, c4 = (i4 & 63) * 4;
            int src = d_act[b*Nn + j0 + r];
            *(float4*)&Ks[r][c4] = *(const float4*)&d_kk[((size_t)(b*Nn) + src)*256 + c4];
            *(float4*)&Gs[r][c4] = *(const float4*)&d_gg[((size_t)(b*Nn) + src)*256 + c4];
        }
        __syncthreads();
        float s = -1e30f;
        if (lane < jn){
            s = 0.f;
            #pragma unroll 4
            for (int c4 = 0; c4 < 64; c4++){
                float4 qv = *(const float4*)&Qs[q][c4*4];
                float4 kv = *(const float4*)&Ks[lane][c4*4];
                s += qv.x*kv.x + qv.y*kv.y + qv.z*kv.z + qv.w*kv.w;
            }
        }
        Ss[q][lane] = s;
        __syncthreads();
        float cmax = rmax;
        for (int j=0;j<jn;j++) cmax = fmaxf(cmax, Ss[q][j]);
        float scale = __expf(rmax - cmax);
        rsum *= scale;
        #pragma unroll
        for (int i=0;i<16;i++) yacc[i] *= scale;
        for (int j=0;j<jn;j++){
            float pj = __expf(Ss[q][j] - cmax);
            rsum += pj;
            #pragma unroll
            for (int i=0;i<16;i++) yacc[i] += pj * Gs[j][lane + i*16];
        }
        rmax = cmax;
        __syncthreads();
    }
    float inv = (rsum > 0.f) ? (1.f/rsum) : 0.f;
    #pragma unroll
    for (int i=0;i<16;i++){
        float v = yacc[i]*inv;
        size_t o = ((size_t)(b*Nn) + q0 + q)*256 + lane + i*16;
        __half h, l; split16(v, h, l);
        d_ph[o] = h; d_pl[o] = l;
    }
}

// ---------------- instance-norm finalize (reads+zeros psum) ----------------
__global__ void k_statf(){
    int b = blockIdx.x, c = threadIdx.x;
    float s  = d_psum[b*256 + c];
    float s2 = d_psum[1024 + b*256 + c];
    float mu = s * (1.f/4096.f);
    float var = s2 * (1.f/4096.f) - mu*mu;
    d_mean[b*256+c] = mu;
    d_rstd[b*256+c] = rsqrtf(var + 1e-5f);
    d_psum[b*256 + c] = 0.f;
    d_psum[1024 + b*256 + c] = 0.f;
}

// relu(IN(t-planes)) -> p-hi plane only (consumer conv is 2-term)
__global__ void k_in_relu(){
    int i2 = blockIdx.x*256 + threadIdx.x;
    int base = i2*2;
    int c = base & 255; int b = base >> 20;
    __half2 h2 = *(const __half2*)&d_th[base];
    __half2 l2 = *(const __half2*)&d_tl[base];
    float v0 = __half2float(h2.x) + __half2float(l2.x);
    float v1 = __half2float(h2.y) + __half2float(l2.y);
    v0 = fmaxf((v0 - d_mean[b*256+c])   * d_rstd[b*256+c],   0.f);
    v1 = fmaxf((v1 - d_mean[b*256+c+1]) * d_rstd[b*256+c+1], 0.f);
    *(__half2*)&d_ph[base] = __halves2half2(__float2half(v0), __float2half(v1));
}
// wy += IN(t-planes); write a-hi plane only (consumer conv is 2-term)
__global__ void k_in_add(float* __restrict__ io){
    int i2 = blockIdx.x*256 + threadIdx.x;
    int base = i2*2;
    int c = base & 255; int b = base >> 20;
    __half2 h2 = *(const __half2*)&d_th[base];
    __half2 l2 = *(const __half2*)&d_tl[base];
    float v0 = __half2float(h2.x) + __half2float(l2.x);
    float v1 = __half2float(h2.y) + __half2float(l2.y);
    float2 w = *(float2*)&io[base];
    w.x += (v0 - d_mean[b*256+c])   * d_rstd[b*256+c];
    w.y += (v1 - d_mean[b*256+c+1]) * d_rstd[b*256+c+1];
    *(float2*)&io[base] = w;
    *(__half2*)&d_ah[base] = __halves2half2(__float2half(w.x), __float2half(w.y));
}

// ---------------- final blend + NHWC->NCHW ----------------
__global__ void k_blend(const float* __restrict__ x, float* __restrict__ z){
    __shared__ float tile[32][33];
    int b = blockIdx.z; int n0 = blockIdx.x*32, c0 = blockIdx.y*32;
    int tx = threadIdx.x, ty = threadIdx.y;
    tile[ty][tx] = d_wy[((size_t)(b*Nn) + n0+ty)*256 + c0+tx];
    __syncthreads();
    int n = n0 + tx, c = c0 + ty;
    float m = d_mk[b*Nn + n];
    size_t idx = ((size_t)(b*Cc + c))*Nn + n;
    z[idx] = m * x[idx] + (1.f - m) * tile[tx][ty];
}

// ---------------- launch ----------------
extern "C" void kernel_launch(void* const* d_in, const int* in_sizes, int n_in,
                              void* d_out, int out_size) {
    (void)in_sizes; (void)n_in; (void)out_size;
    const float* x    = (const float*)d_in[0];
    const float* mask = (const float*)d_in[1];
    const float* g_w  = (const float*)d_in[2];
    const float* g_b  = (const float*)d_in[3];
    const float* th_w = (const float*)d_in[4];
    const float* th_b = (const float*)d_in[5];
    const float* ph_w = (const float*)d_in[6];
    const float* ph_b = (const float*)d_in[7];
    const float* W_w  = (const float*)d_in[8];
    const float* W_b  = (const float*)d_in[9];
    const float* rw1  = (const float*)d_in[10];
    const float* rb1  = (const float*)d_in[11];
    const float* rw2  = (const float*)d_in[12];
    const float* rb2  = (const float*)d_in[13];
    float* z = (float*)d_out;

    cudaFuncSetAttribute(k_tmm,  cudaFuncAttributeMaxDynamicSharedMemorySize, TM_SMEM_TOTAL);
    cudaFuncSetAttribute(k_tmmc, cudaFuncAttributeMaxDynamicSharedMemorySize, TC_SMEM_TOTAL);

    float *pq, *pk, *pg, *pwy, *pps;
    __half *pah, *pal, *pph, *ppl, *pth, *ptl, *pwbh, *pwbl, *pw1h, *pw1l;
    cudaGetSymbolAddress((void**)&pq,  d_q);
    cudaGetSymbolAddress((void**)&pk,  d_kk);
    cudaGetSymbolAddress((void**)&pg,  d_gg);
    cudaGetSymbolAddress((void**)&pwy, d_wy);
    cudaGetSymbolAddress((void**)&pps, d_psum);
    cudaGetSymbolAddress((void**)&pah, d_ah);
    cudaGetSymbolAddress((void**)&pal, d_al);
    cudaGetSymbolAddress((void**)&pph, d_ph);
    cudaGetSymbolAddress((void**)&ppl, d_pl);
    cudaGetSymbolAddress((void**)&pth, d_th);
    cudaGetSymbolAddress((void**)&ptl, d_tl);
    cudaGetSymbolAddress((void**)&pwbh, d_wbh);
    cudaGetSymbolAddress((void**)&pwbl, d_wbl);
    cudaGetSymbolAddress((void**)&pw1h, d_w1h);
    cudaGetSymbolAddress((void**)&pw1l, d_w1l);

    dim3 t32(32,32);
    k_wconv<<<14848, 256>>>(rw1, rw2, g_w, th_w, ph_w, W_w);
    k_xt  <<<dim3(128,8,4), t32>>>(x);
    k_mask<<<4, 1024>>>(mask);

    dim3 gg(2,128);
    k_tmm<<<gg,256,TM_SMEM_TOTAL>>>(pah, pal, pw1h+1*65536, pw1l+1*65536, th_b, pq, 0, 0);
    k_tmm<<<gg,256,TM_SMEM_TOTAL>>>(pah, pal, pw1h+2*65536, pw1l+2*65536, ph_b, pk, 0, 0);
    k_tmm<<<gg,256,TM_SMEM_TOTAL>>>(pah, pal, pw1h+0*65536, pw1l+0*65536, g_b,  pg, 0, 0);

    k_attn<<<dim3(256,4),256>>>();   // -> p-planes (hi+lo)

    // W 1x1: p-planes -> wy fp32 + a-planes (hi+lo)
    k_tmm<<<gg,256,TM_SMEM_TOTAL>>>(pph, ppl, pw1h+3*65536, pw1l+3*65536, W_b, pwy, pah, pal);

    for (int i=0;i<3;i++){
        k_tmmc<<<gg,256,TC_SMEM_TOTAL>>>(pah, pwbh + (size_t)(2*i)*9*65536,
                                         pwbl + (size_t)(2*i)*9*65536, rb1 + i*256,
                                         pth, ptl, pps);
        k_statf<<<4,256>>>();
        k_in_relu<<<8192,256>>>();
        k_tmmc<<<gg,256,TC_SMEM_TOTAL>>>(pph, pwbh + (size_t)(2*i+1)*9*65536,
                                         pwbl + (size_t)(2*i+1)*9*65536, rb2 + i*256,
                                         pth, ptl, pps);
        k_statf<<<4,256>>>();
        k_in_add<<<8192,256>>>(pwy);
    }

    k_blend<<<dim3(128,8,4), t32>>>(x, z);
}

// round 15
// speedup vs baseline: 2.6551x; 1.0016x over previous
#include <cuda_runtime.h>
#include <cuda_fp16.h>
#include <math.h>
#include <stdint.h>

#define Bn 4
#define Cc 256
#define Nn 4096
#define Mm (Bn*Nn)   // 16384

// ---------------- helpers ----------------
__device__ __forceinline__ uint32_t smem_u32(const void* p){
    uint32_t a;
    asm("{ .reg .u64 t; cvta.to.shared.u64 t, %1; cvt.u32.u64 %0, t; }" : "=r"(a) : "l"(p));
    return a;
}
__device__ __forceinline__ int refl(int i, int n){ return i<0 ? -i : (i>=n ? 2*n-2-i : i); }

__device__ __forceinline__ void cpasync16(uint32_t dst, const void* src){
    asm volatile("cp.async.cg.shared.global [%0], [%1], 16;" :: "r"(dst), "l"(src) : "memory");
}
__device__ __forceinline__ void ldsm4(uint32_t (&r)[4], uint32_t addr){
    asm volatile("ldmatrix.sync.aligned.m8n8.x4.shared.b16 {%0,%1,%2,%3}, [%4];"
        : "=r"(r[0]), "=r"(r[1]), "=r"(r[2]), "=r"(r[3]) : "r"(addr));
}
__device__ __forceinline__ void mma16816(float (&d)[4], const uint32_t (&a)[4], const uint32_t* b){
    asm volatile("mma.sync.aligned.m16n8k16.row.col.f32.f16.f16.f32 "
        "{%0,%1,%2,%3},{%4,%5,%6,%7},{%8,%9},{%0,%1,%2,%3};"
        : "+f"(d[0]), "+f"(d[1]), "+f"(d[2]), "+f"(d[3])
        : "r"(a[0]), "r"(a[1]), "r"(a[2]), "r"(a[3]), "r"(b[0]), "r"(b[1]));
}
__device__ __forceinline__ void split16(float v, __half &h, __half &l){
    h = __float2half(v);
    l = __float2half(v - __half2float(h));
}

// ---------------- scratch (device globals) ----------------
__device__ float d_q [Mm*Cc];
__device__ float d_kk[Mm*Cc];
__device__ float d_gg[Mm*Cc];
__device__ float d_wy[Mm*Cc];
__device__ __half d_ah[Mm*Cc];   // activation planes
__device__ __half d_al[Mm*Cc];
__device__ __half d_ph[Mm*Cc];   // post-relu / attention-out planes
__device__ __half d_pl[Mm*Cc];
__device__ __half d_th[Mm*Cc];   // conv output planes (pre-IN)
__device__ __half d_tl[Mm*Cc];
__device__ __half d_wbh[6*9*Cc*Cc];
__device__ __half d_wbl[6*9*Cc*Cc];
__device__ __half d_w1h[4*Cc*Cc];
__device__ __half d_w1l[4*Cc*Cc];
__device__ float d_mk[Mm];
__device__ int   d_act[Mm];
__device__ int   d_cnt[Bn];
__device__ float d_psum[2*Bn*Cc];   // zero-init; k_statf re-zeros after use
__device__ float d_mean[Bn*Cc];
__device__ float d_rstd[Bn*Cc];

// ---------------- weight conversion fp32 -> fp16 hi/lo ----------------
__global__ void k_wconv(const float* __restrict__ rw1, const float* __restrict__ rw2,
                        const float* __restrict__ gw, const float* __restrict__ tw,
                        const float* __restrict__ pw, const float* __restrict__ Ww){
    int idx = blockIdx.x*256 + threadIdx.x;
    const int NC = 6*9*65536;
    if (idx < NC){
        int cv = idx / (9*65536);
        int rem = idx - cv*(9*65536);
        int tap = rem >> 16;
        int oc = rem & 65535;
        int o = oc >> 8, c = oc & 255;
        int i = cv >> 1;
        const float* rw = (cv & 1) ? rw2 : rw1;
        float v = rw[(((i*256 + o)*256 + c)*9) + tap];
        __half h, l; split16(v, h, l);
        d_wbh[idx] = h; d_wbl[idx] = l;
    } else if (idx < NC + 4*65536){
        int j = idx - NC;
        int mat = j >> 16;
        int oc = j & 65535;
        const float* src = (mat==0) ? gw : (mat==1) ? tw : (mat==2) ? pw : Ww;
        __half h, l; split16(src[oc], h, l);
        d_w1h[j] = h; d_w1l[j] = l;
    }
}

// ---------------- x: NCHW -> fp16 hi/lo [B,N,C] ----------------
__global__ void k_xt(const float* __restrict__ x){
    __shared__ float tile[32][33];
    int b = blockIdx.z; int n0 = blockIdx.x*32, c0 = blockIdx.y*32;
    int tx = threadIdx.x, ty = threadIdx.y;
    tile[ty][tx] = x[((size_t)(b*Cc) + c0+ty)*Nn + n0+tx];
    __syncthreads();
    size_t o = ((size_t)(b*Nn) + n0+ty)*Cc + c0+tx;
    __half h, l; split16(tile[tx][ty], h, l);
    d_ah[o] = h; d_al[o] = l;
}

// ---------------- mask + active-key compaction ----------------
__global__ void k_mask(const float* __restrict__ mask){
    int b = blockIdx.x, t = threadIdx.x;
    __shared__ int sc[1024];
    const float* mb = mask + b*32*32;
    int flag[4]; int cnt = 0;
    #pragma unroll
    for (int i=0;i<4;i++){
        int n = t*4+i; int h = n>>6, w = n&63;
        float fy = h*0.5f - 0.25f, fx = w*0.5f - 0.25f;
        int y0 = (int)floorf(fy), x0 = (int)floorf(fx);
        float wy1 = fy - (float)y0, wx1 = fx - (float)x0;
        int y0c = min(max(y0,0),31), y1c = min(max(y0+1,0),31);
        int x0c = min(max(x0,0),31), x1c = min(max(x0+1,0),31);
        float v = (mb[y0c*32+x0c]*(1.f-wx1) + mb[y0c*32+x1c]*wx1)*(1.f-wy1)
                + (mb[y1c*32+x0c]*(1.f-wx1) + mb[y1c*32+x1c]*wx1)*wy1;
        float mv = (v > 0.f) ? 1.f : v;
        float a = 1.f - mv;
        float tmp = 1.f - mb[(h>>1)*32 + (w>>1)];
        float m = a * tmp;
        d_mk[b*Nn + n] = m;
        flag[i] = (m > 0.5f) ? 1 : 0;
        cnt += flag[i];
    }
    sc[t] = cnt; __syncthreads();
    for (int s=1; s<1024; s<<=1){
        int v = (t >= s) ? sc[t-s] : 0;
        __syncthreads();
        sc[t] += v;
        __syncthreads();
    }
    int base = sc[t] - cnt;
    #pragma unroll
    for (int i=0;i<4;i++) if (flag[i]) d_act[b*Nn + (base++)] = t*4+i;
    if (t == 1023) d_cnt[b] = sc[1023];
}

#define PLANE 8192
// ================= 3-term 1x1 GEMM kernel (ldsm interleaved into mma stream) ==
#define STAGE (4*PLANE)           // 32768
#define TM_SMEM_TOTAL (3*STAGE)   // 98304

__device__ __forceinline__ void tmm_load(uint32_t st,
    const __half* __restrict__ Ah, const __half* __restrict__ Al,
    const __half* __restrict__ Wh, const __half* __restrict__ Wl,
    int m0, int n0, int chunk, int t)
{
    int k0 = (chunk & 7)*32;
    #pragma unroll
    for (int it=0; it<2; it++){
        int e = t + it*256;
        int r = e >> 2, ch = e & 3;
        int slot = ch ^ ((r >> 1) & 3);
        uint32_t dst = st + r*64 + (slot << 4);
        size_t srcA = (size_t)(m0 + r)*256 + k0 + ch*8;
        cpasync16(dst,         Ah + srcA);
        cpasync16(dst + PLANE, Al + srcA);
        size_t srcB = ((size_t)(n0 + r))*256 + k0 + ch*8;
        cpasync16(dst + 2*PLANE, Wh + srcB);
        cpasync16(dst + 3*PLANE, Wl + srcB);
    }
}

__global__ void __launch_bounds__(256, 2)
k_tmm(const __half* __restrict__ Ah, const __half* __restrict__ Al,
      const __half* __restrict__ Wh, const __half* __restrict__ Wl,
      const float* __restrict__ bias, float* __restrict__ Cout,
      __half* __restrict__ Oh, __half* __restrict__ Ol)
{
    extern __shared__ char smem[];
    uint32_t sb = smem_u32(smem);
    int t = threadIdx.x, lane = t & 31, wid = t >> 5;
    int warp_m = wid & 3, warp_n = wid >> 2;
    int n0 = blockIdx.x * 128, m0 = blockIdx.y * 128;

    const int S = 8;
    float acc[2][8][4] = {};

    tmm_load(sb,         Ah, Al, Wh, Wl, m0, n0, 0, t);
    asm volatile("cp.async.commit_group;" ::: "memory");
    tmm_load(sb + STAGE, Ah, Al, Wh, Wl, m0, n0, 1, t);
    asm volatile("cp.async.commit_group;" ::: "memory");

    int rA  = warp_m*32 + (lane & 15);
    int hiA = lane >> 4;
    int sxA = (rA >> 1) & 3;
    uint32_t aRow = (uint32_t)rA * 64;
    int rB  = warp_n*64 + (lane & 7) + ((lane >> 4) << 3);
    int gB  = (lane >> 3) & 1;
    int sxB = (rB >> 1) & 3;
    uint32_t bRow = (uint32_t)rB * 64;

    for (int i = 0; i < S; i++){
        int rem = S - 1 - i;
        if (rem >= 1) asm volatile("cp.async.wait_group 1;" ::: "memory");
        else          asm volatile("cp.async.wait_group 0;" ::: "memory");
        __syncthreads();
        if (i + 2 < S){
            tmm_load(sb + (uint32_t)((i+2)%3)*STAGE, Ah, Al, Wh, Wl, m0, n0, i+2, t);
            asm volatile("cp.async.commit_group;" ::: "memory");
        }
        uint32_t st = sb + (uint32_t)(i%3)*STAGE;
        #pragma unroll
        for (int kk = 0; kk < 2; kk++){
            uint32_t aAddr = st + aRow + ((uint32_t)(((2*kk) + hiA) ^ sxA) << 4);
            uint32_t aH[2][4], aL[2][4];
            ldsm4(aH[0], aAddr);
            ldsm4(aH[1], aAddr + 16*64);
            #pragma unroll
            for (int ng = 0; ng < 2; ng++){
                uint32_t bAddr = st + 2*PLANE + bRow + (uint32_t)(ng*32*64)
                               + ((uint32_t)(((2*kk) + gB) ^ sxB) << 4);
                uint32_t bH[8], bL[8];
                ldsm4(*(uint32_t(*)[4])&bH[0], bAddr);
                ldsm4(*(uint32_t(*)[4])&bH[4], bAddr + 16*64);
                // hi-term mmas while bL/aL loads stream in behind them
                #pragma unroll
                for (int j = 0; j < 4; j++){
                    int nt = ng*4 + j;
                    #pragma unroll
                    for (int mt = 0; mt < 2; mt++)
                        mma16816(acc[mt][nt], aH[mt], &bH[2*j]);
                }
                ldsm4(*(uint32_t(*)[4])&bL[0], bAddr + PLANE);
                ldsm4(*(uint32_t(*)[4])&bL[4], bAddr + PLANE + 16*64);
                #pragma unroll
                for (int j = 0; j < 4; j++){
                    int nt = ng*4 + j;
                    #pragma unroll
                    for (int mt = 0; mt < 2; mt++)
                        mma16816(acc[mt][nt], aH[mt], &bL[2*j]);
                }
                if (ng == 0){
                    ldsm4(aL[0], aAddr + PLANE);
                    ldsm4(aL[1], aAddr + PLANE + 16*64);
                }
                #pragma unroll
                for (int j = 0; j < 4; j++){
                    int nt = ng*4 + j;
                    #pragma unroll
                    for (int mt = 0; mt < 2; mt++)
                        mma16816(acc[mt][nt], aL[mt], &bH[2*j]);
                }
            }
        }
    }

    int rbase = m0 + warp_m*32;
    int nb = n0 + warp_n*64;
    int rr = lane >> 2, c2 = 2*(lane & 3);
    #pragma unroll
    for (int mt = 0; mt < 2; mt++){
        #pragma unroll
        for (int nt = 0; nt < 8; nt++){
            int row = rbase + mt*16 + rr;
            int col = nb + nt*8 + c2;
            float b0 = bias[col], b1 = bias[col+1];
            float v00 = acc[mt][nt][0] + b0, v01 = acc[mt][nt][1] + b1;
            float v10 = acc[mt][nt][2] + b0, v11 = acc[mt][nt][3] + b1;
            if (Cout){
                float2 p0; p0.x = v00; p0.y = v01;
                float2 p1; p1.x = v10; p1.y = v11;
                *(float2*)&Cout[(size_t)row*256 + col] = p0;
                *(float2*)&Cout[(size_t)(row+8)*256 + col] = p1;
            }
            if (Oh){
                __half h00, l00, h01, l01, h10, l10, h11, l11;
                split16(v00, h00, l00); split16(v01, h01, l01);
                split16(v10, h10, l10); split16(v11, h11, l11);
                *(__half2*)&Oh[(size_t)row*256 + col]     = __halves2half2(h00, h01);
                *(__half2*)&Ol[(size_t)row*256 + col]     = __halves2half2(l00, l01);
                *(__half2*)&Oh[(size_t)(row+8)*256 + col] = __halves2half2(h10, h11);
                *(__half2*)&Ol[(size_t)(row+8)*256 + col] = __halves2half2(l10, l11);
            }
        }
    }
}

// ================= 2-term conv kernel: D = Ah @ (Wh + Wl) =================
// 3 planes per stage (A, Bh, Bl) = 24KB, 4 stages, ONE barrier per chunk pair.
// bL ldsm interleaved after the hi-mma block to time-spread crossbar demand.
#define STAGE3 (3*PLANE)            // 24576
#define TC_SMEM_TOTAL (4*STAGE3)    // 98304

__device__ __forceinline__ void tmmc_load(uint32_t st,
    const __half* __restrict__ Ah,
    const __half* __restrict__ Wh, const __half* __restrict__ Wl,
    int m0, int n0, int chunk, int t)
{
    int tap = chunk >> 3, k0 = (chunk & 7)*32;
    int dy = tap/3 - 1, dx = tap%3 - 1;
    #pragma unroll
    for (int it=0; it<2; it++){
        int e = t + it*256;
        int r = e >> 2, ch = e & 3;
        int slot = ch ^ ((r >> 1) & 3);
        uint32_t dst = st + r*64 + (slot << 4);
        int gg = m0 + r, b = gg >> 12, p = gg & 4095, h = p >> 6, w = p & 63;
        int grow = (b << 12) + (refl(h+dy,64) << 6) + refl(w+dx,64);
        cpasync16(dst, Ah + (size_t)grow*256 + k0 + ch*8);
        size_t srcB = ((size_t)tap*256 + n0 + r)*256 + k0 + ch*8;
        cpasync16(dst + PLANE,   Wh + srcB);
        cpasync16(dst + 2*PLANE, Wl + srcB);
    }
}

__global__ void __launch_bounds__(256, 2)
k_tmmc(const __half* __restrict__ Ah,
       const __half* __restrict__ Wh, const __half* __restrict__ Wl,
       const float* __restrict__ bias,
       __half* __restrict__ Oh, __half* __restrict__ Ol,
       float* __restrict__ psum)
{
    extern __shared__ char smem[];
    uint32_t sb = smem_u32(smem);
    int t = threadIdx.x, lane = t & 31, wid = t >> 5;
    int warp_m = wid & 3, warp_n = wid >> 2;
    int n0 = blockIdx.x * 128, m0 = blockIdx.y * 128;

    const int S = 72;
    float acc[2][8][4] = {};

    tmmc_load(sb,          Ah, Wh, Wl, m0, n0, 0, t);
    tmmc_load(sb + STAGE3, Ah, Wh, Wl, m0, n0, 1, t);
    asm volatile("cp.async.commit_group;" ::: "memory");

    int rA  = warp_m*32 + (lane & 15);
    int hiA = lane >> 4;
    int sxA = (rA >> 1) & 3;
    uint32_t aRow = (uint32_t)rA * 64;
    int rB  = warp_n*64 + (lane & 7) + ((lane >> 4) << 3);
    int gB  = (lane >> 3) & 1;
    int sxB = (rB >> 1) & 3;
    uint32_t bRow = (uint32_t)rB * 64;

    for (int p = 0; p < S/2; p++){
        asm volatile("cp.async.wait_group 0;" ::: "memory");
        __syncthreads();
        if (2*p + 2 < S){
            tmmc_load(sb + (uint32_t)((2*p+2)&3)*STAGE3, Ah, Wh, Wl, m0, n0, 2*p+2, t);
            tmmc_load(sb + (uint32_t)((2*p+3)&3)*STAGE3, Ah, Wh, Wl, m0, n0, 2*p+3, t);
            asm volatile("cp.async.commit_group;" ::: "memory");
        }
        #pragma unroll
        for (int q = 0; q < 2; q++){
            uint32_t st = sb + (uint32_t)((2*p+q)&3)*STAGE3;
            #pragma unroll
            for (int kk = 0; kk < 2; kk++){
                uint32_t aAddr = st + aRow + ((uint32_t)(((2*kk) + hiA) ^ sxA) << 4);
                uint32_t aH[2][4];
                ldsm4(aH[0], aAddr);
                ldsm4(aH[1], aAddr + 16*64);
                #pragma unroll
                for (int ng = 0; ng < 2; ng++){
                    uint32_t bAddr = st + PLANE + bRow + (uint32_t)(ng*32*64)
                                   + ((uint32_t)(((2*kk) + gB) ^ sxB) << 4);
                    uint32_t bH[8], bL[8];
                    ldsm4(*(uint32_t(*)[4])&bH[0], bAddr);
                    ldsm4(*(uint32_t(*)[4])&bH[4], bAddr + 16*64);
                    // hi mmas run while bL streams in behind them
                    #pragma unroll
                    for (int j = 0; j < 4; j++){
                        int nt = ng*4 + j;
                        #pragma unroll
                        for (int mt = 0; mt < 2; mt++)
                            mma16816(acc[mt][nt], aH[mt], &bH[2*j]);
                    }
                    ldsm4(*(uint32_t(*)[4])&bL[0], bAddr + PLANE);
                    ldsm4(*(uint32_t(*)[4])&bL[4], bAddr + PLANE + 16*64);
                    #pragma unroll
                    for (int j = 0; j < 4; j++){
                        int nt = ng*4 + j;
                        #pragma unroll
                        for (int mt = 0; mt < 2; mt++)
                            mma16816(acc[mt][nt], aH[mt], &bL[2*j]);
                    }
                }
            }
        }
    }

    // ---- epilogue: planes + fused IN stats ----
    int rbase = m0 + warp_m*32;
    int nb = n0 + warp_n*64;
    int rr = lane >> 2, c2 = 2*(lane & 3);
    float cs[16] = {}, cs2[16] = {};
    #pragma unroll
    for (int mt = 0; mt < 2; mt++){
        #pragma unroll
        for (int nt = 0; nt < 8; nt++){
            int row = rbase + mt*16 + rr;
            int col = nb + nt*8 + c2;
            float b0 = bias[col], b1 = bias[col+1];
            float v00 = acc[mt][nt][0] + b0, v01 = acc[mt][nt][1] + b1;
            float v10 = acc[mt][nt][2] + b0, v11 = acc[mt][nt][3] + b1;
            __half h00, l00, h01, l01, h10, l10, h11, l11;
            split16(v00, h00, l00); split16(v01, h01, l01);
            split16(v10, h10, l10); split16(v11, h11, l11);
            *(__half2*)&Oh[(size_t)row*256 + col]     = __halves2half2(h00, h01);
            *(__half2*)&Ol[(size_t)row*256 + col]     = __halves2half2(l00, l01);
            *(__half2*)&Oh[(size_t)(row+8)*256 + col] = __halves2half2(h10, h11);
            *(__half2*)&Ol[(size_t)(row+8)*256 + col] = __halves2half2(l10, l11);
            cs [nt*2]   += v00 + v10;
            cs [nt*2+1] += v01 + v11;
            cs2[nt*2]   += v00*v00 + v10*v10;
            cs2[nt*2+1] += v01*v01 + v11*v11;
        }
    }
    #pragma unroll
    for (int o = 4; o <= 16; o <<= 1){
        #pragma unroll
        for (int j = 0; j < 16; j++){
            cs[j]  += __shfl_xor_sync(0xffffffffu, cs[j],  o);
            cs2[j] += __shfl_xor_sync(0xffffffffu, cs2[j], o);
        }
    }
    if (lane < 4){
        int b = m0 >> 12;
        #pragma unroll
        for (int nt = 0; nt < 8; nt++){
            int col = nb + nt*8 + 2*lane;
            atomicAdd(&psum[b*256 + col],          cs [2*nt]);
            atomicAdd(&psum[b*256 + col + 1],      cs [2*nt+1]);
            atomicAdd(&psum[1024 + b*256 + col],   cs2[2*nt]);
            atomicAdd(&psum[1024 + b*256 + col+1], cs2[2*nt+1]);
        }
    }
}

// ---------------- masked-softmax attention over compacted keys ----------------
__global__ void __launch_bounds__(256) k_attn(){
    int b = blockIdx.y; int q0 = blockIdx.x * 16;
    __shared__ float Qs[16][260];
    __shared__ float Ks[16][260];
    __shared__ float Gs[16][260];
    __shared__ float Ss[16][17];
    int t = threadIdx.x;
    for (int i4 = t; i4 < 16*64; i4 += 256){
        int r = i4 >> 6, c4 = (i4 & 63) * 4;
        *(float4*)&Qs[r][c4] = *(const float4*)&d_q[((size_t)(b*Nn) + q0 + r)*256 + c4];
    }
    int cnt = d_cnt[b];
    int q = t >> 4, lane = t & 15;
    float yacc[16];
    #pragma unroll
    for (int i=0;i<16;i++) yacc[i] = 0.f;
    float rmax = -1e30f, rsum = 0.f;
    __syncthreads();
    for (int j0=0; j0<cnt; j0+=16){
        int jn = min(16, cnt - j0);
        for (int i4 = t; i4 < jn*64; i4 += 256){
            int r = i4 >> 6, c4 = (i4 & 63) * 4;
            int src = d_act[b*Nn + j0 + r];
            *(float4*)&Ks[r][c4] = *(const float4*)&d_kk[((size_t)(b*Nn) + src)*256 + c4];
            *(float4*)&Gs[r][c4] = *(const float4*)&d_gg[((size_t)(b*Nn) + src)*256 + c4];
        }
        __syncthreads();
        float s = -1e30f;
        if (lane < jn){
            s = 0.f;
            #pragma unroll 4
            for (int c4 = 0; c4 < 64; c4++){
                float4 qv = *(const float4*)&Qs[q][c4*4];
                float4 kv = *(const float4*)&Ks[lane][c4*4];
                s += qv.x*kv.x + qv.y*kv.y + qv.z*kv.z + qv.w*kv.w;
            }
        }
        Ss[q][lane] = s;
        __syncthreads();
        float cmax = rmax;
        for (int j=0;j<jn;j++) cmax = fmaxf(cmax, Ss[q][j]);
        float scale = __expf(rmax - cmax);
        rsum *= scale;
        #pragma unroll
        for (int i=0;i<16;i++) yacc[i] *= scale;
        for (int j=0;j<jn;j++){
            float pj = __expf(Ss[q][j] - cmax);
            rsum += pj;
            #pragma unroll
            for (int i=0;i<16;i++) yacc[i] += pj * Gs[j][lane + i*16];
        }
        rmax = cmax;
        __syncthreads();
    }
    float inv = (rsum > 0.f) ? (1.f/rsum) : 0.f;
    #pragma unroll
    for (int i=0;i<16;i++){
        float v = yacc[i]*inv;
        size_t o = ((size_t)(b*Nn) + q0 + q)*256 + lane + i*16;
        __half h, l; split16(v, h, l);
        d_ph[o] = h; d_pl[o] = l;
    }
}

// ---------------- instance-norm finalize (reads+zeros psum) ----------------
__global__ void k_statf(){
    int b = blockIdx.x, c = threadIdx.x;
    float s  = d_psum[b*256 + c];
    float s2 = d_psum[1024 + b*256 + c];
    float mu = s * (1.f/4096.f);
    float var = s2 * (1.f/4096.f) - mu*mu;
    d_mean[b*256+c] = mu;
    d_rstd[b*256+c] = rsqrtf(var + 1e-5f);
    d_psum[b*256 + c] = 0.f;
    d_psum[1024 + b*256 + c] = 0.f;
}

// relu(IN(t-planes)) -> p-hi plane only (consumer conv is 2-term)
__global__ void k_in_relu(){
    int i2 = blockIdx.x*256 + threadIdx.x;
    int base = i2*2;
    int c = base & 255; int b = base >> 20;
    __half2 h2 = *(const __half2*)&d_th[base];
    __half2 l2 = *(const __half2*)&d_tl[base];
    float v0 = __half2float(h2.x) + __half2float(l2.x);
    float v1 = __half2float(h2.y) + __half2float(l2.y);
    v0 = fmaxf((v0 - d_mean[b*256+c])   * d_rstd[b*256+c],   0.f);
    v1 = fmaxf((v1 - d_mean[b*256+c+1]) * d_rstd[b*256+c+1], 0.f);
    *(__half2*)&d_ph[base] = __halves2half2(__float2half(v0), __float2half(v1));
}
// wy += IN(t-planes); write a-hi plane only (consumer conv is 2-term)
__global__ void k_in_add(float* __restrict__ io){
    int i2 = blockIdx.x*256 + threadIdx.x;
    int base = i2*2;
    int c = base & 255; int b = base >> 20;
    __half2 h2 = *(const __half2*)&d_th[base];
    __half2 l2 = *(const __half2*)&d_tl[base];
    float v0 = __half2float(h2.x) + __half2float(l2.x);
    float v1 = __half2float(h2.y) + __half2float(l2.y);
    float2 w = *(float2*)&io[base];
    w.x += (v0 - d_mean[b*256+c])   * d_rstd[b*256+c];
    w.y += (v1 - d_mean[b*256+c+1]) * d_rstd[b*256+c+1];
    *(float2*)&io[base] = w;
    *(__half2*)&d_ah[base] = __halves2half2(__float2half(w.x), __float2half(w.y));
}

// ---------------- final blend + NHWC->NCHW ----------------
__global__ void k_blend(const float* __restrict__ x, float* __restrict__ z){
    __shared__ float tile[32][33];
    int b = blockIdx.z; int n0 = blockIdx.x*32, c0 = blockIdx.y*32;
    int tx = threadIdx.x, ty = threadIdx.y;
    tile[ty][tx] = d_wy[((size_t)(b*Nn) + n0+ty)*256 + c0+tx];
    __syncthreads();
    int n = n0 + tx, c = c0 + ty;
    float m = d_mk[b*Nn + n];
    size_t idx = ((size_t)(b*Cc + c))*Nn + n;
    z[idx] = m * x[idx] + (1.f - m) * tile[tx][ty];
}

// ---------------- launch ----------------
extern "C" void kernel_launch(void* const* d_in, const int* in_sizes, int n_in,
                              void* d_out, int out_size) {
    (void)in_sizes; (void)n_in; (void)out_size;
    const float* x    = (const float*)d_in[0];
    const float* mask = (const float*)d_in[1];
    const float* g_w  = (const float*)d_in[2];
    const float* g_b  = (const float*)d_in[3];
    const float* th_w = (const float*)d_in[4];
    const float* th_b = (const float*)d_in[5];
    const float* ph_w = (const float*)d_in[6];
    const float* ph_b = (const float*)d_in[7];
    const float* W_w  = (const float*)d_in[8];
    const float* W_b  = (const float*)d_in[9];
    const float* rw1  = (const float*)d_in[10];
    const float* rb1  = (const float*)d_in[11];
    const float* rw2  = (const float*)d_in[12];
    const float* rb2  = (const float*)d_in[13];
    float* z = (float*)d_out;

    cudaFuncSetAttribute(k_tmm,  cudaFuncAttributeMaxDynamicSharedMemorySize, TM_SMEM_TOTAL);
    cudaFuncSetAttribute(k_tmmc, cudaFuncAttributeMaxDynamicSharedMemorySize, TC_SMEM_TOTAL);

    float *pq, *pk, *pg, *pwy, *pps;
    __half *pah, *pal, *pph, *ppl, *pth, *ptl, *pwbh, *pwbl, *pw1h, *pw1l;
    cudaGetSymbolAddress((void**)&pq,  d_q);
    cudaGetSymbolAddress((void**)&pk,  d_kk);
    cudaGetSymbolAddress((void**)&pg,  d_gg);
    cudaGetSymbolAddress((void**)&pwy, d_wy);
    cudaGetSymbolAddress((void**)&pps, d_psum);
    cudaGetSymbolAddress((void**)&pah, d_ah);
    cudaGetSymbolAddress((void**)&pal, d_al);
    cudaGetSymbolAddress((void**)&pph, d_ph);
    cudaGetSymbolAddress((void**)&ppl, d_pl);
    cudaGetSymbolAddress((void**)&pth, d_th);
    cudaGetSymbolAddress((void**)&ptl, d_tl);
    cudaGetSymbolAddress((void**)&pwbh, d_wbh);
    cudaGetSymbolAddress((void**)&pwbl, d_wbl);
    cudaGetSymbolAddress((void**)&pw1h, d_w1h);
    cudaGetSymbolAddress((void**)&pw1l, d_w1l);

    dim3 t32(32,32);
    k_wconv<<<14848, 256>>>(rw1, rw2, g_w, th_w, ph_w, W_w);
    k_xt  <<<dim3(128,8,4), t32>>>(x);
    k_mask<<<4, 1024>>>(mask);

    dim3 gg(2,128);
    k_tmm<<<gg,256,TM_SMEM_TOTAL>>>(pah, pal, pw1h+1*65536, pw1l+1*65536, th_b, pq, 0, 0);
    k_tmm<<<gg,256,TM_SMEM_TOTAL>>>(pah, pal, pw1h+2*65536, pw1l+2*65536, ph_b, pk, 0, 0);
    k_tmm<<<gg,256,TM_SMEM_TOTAL>>>(pah, pal, pw1h+0*65536, pw1l+0*65536, g_b,  pg, 0, 0);

    k_attn<<<dim3(256,4),256>>>();   // -> p-planes (hi+lo)

    // W 1x1: p-planes -> wy fp32 + a-planes (hi+lo)
    k_tmm<<<gg,256,TM_SMEM_TOTAL>>>(pph, ppl, pw1h+3*65536, pw1l+3*65536, W_b, pwy, pah, pal);

    for (int i=0;i<3;i++){
        k_tmmc<<<gg,256,TC_SMEM_TOTAL>>>(pah, pwbh + (size_t)(2*i)*9*65536,
                                         pwbl + (size_t)(2*i)*9*65536, rb1 + i*256,
                                         pth, ptl, pps);
        k_statf<<<4,256>>>();
        k_in_relu<<<8192,256>>>();
        k_tmmc<<<gg,256,TC_SMEM_TOTAL>>>(pph, pwbh + (size_t)(2*i+1)*9*65536,
                                         pwbl + (size_t)(2*i+1)*9*65536, rb2 + i*256,
                                         pth, ptl, pps);
        k_statf<<<4,256>>>();
        k_in_add<<<8192,256>>>(pwy);
    }

    k_blend<<<dim3(128,8,4), t32>>>(x, z);
}

// round 16
// speedup vs baseline: 2.6781x; 1.0087x over previous
#include <cuda_runtime.h>
#include <cuda_fp16.h>
#include <math.h>
#include <stdint.h>

#define Bn 4
#define Cc 256
#define Nn 4096
#define Mm (Bn*Nn)   // 16384

// ---------------- helpers ----------------
__device__ __forceinline__ uint32_t smem_u32(const void* p){
    uint32_t a;
    asm("{ .reg .u64 t; cvta.to.shared.u64 t, %1; cvt.u32.u64 %0, t; }" : "=r"(a) : "l"(p));
    return a;
}
__device__ __forceinline__ int refl(int i, int n){ return i<0 ? -i : (i>=n ? 2*n-2-i : i); }

__device__ __forceinline__ void cpasync16(uint32_t dst, const void* src){
    asm volatile("cp.async.cg.shared.global [%0], [%1], 16;" :: "r"(dst), "l"(src) : "memory");
}
__device__ __forceinline__ void ldsm4(uint32_t (&r)[4], uint32_t addr){
    asm volatile("ldmatrix.sync.aligned.m8n8.x4.shared.b16 {%0,%1,%2,%3}, [%4];"
        : "=r"(r[0]), "=r"(r[1]), "=r"(r[2]), "=r"(r[3]) : "r"(addr));
}
__device__ __forceinline__ void mma16816(float (&d)[4], const uint32_t (&a)[4], const uint32_t* b){
    asm volatile("mma.sync.aligned.m16n8k16.row.col.f32.f16.f16.f32 "
        "{%0,%1,%2,%3},{%4,%5,%6,%7},{%8,%9},{%0,%1,%2,%3};"
        : "+f"(d[0]), "+f"(d[1]), "+f"(d[2]), "+f"(d[3])
        : "r"(a[0]), "r"(a[1]), "r"(a[2]), "r"(a[3]), "r"(b[0]), "r"(b[1]));
}
__device__ __forceinline__ void split16(float v, __half &h, __half &l){
    h = __float2half(v);
    l = __float2half(v - __half2float(h));
}

// ---------------- scratch (device globals) ----------------
__device__ float d_q [Mm*Cc];
__device__ float d_kk[Mm*Cc];
__device__ float d_gg[Mm*Cc];
__device__ __half d_wyh[Mm*Cc];  // residual stream (fp16)
__device__ __half d_ah[Mm*Cc];   // x planes (QKG input, hi/lo)
__device__ __half d_al[Mm*Cc];
__device__ __half d_ph[Mm*Cc];   // post-relu / attention-out planes
__device__ __half d_pl[Mm*Cc];
__device__ __half d_th[Mm*Cc];   // conv output planes (pre-IN)
__device__ __half d_tl[Mm*Cc];
__device__ __half d_wbh[6*9*Cc*Cc];
__device__ __half d_wbl[6*9*Cc*Cc];
__device__ __half d_w1h[4*Cc*Cc];
__device__ __half d_w1l[4*Cc*Cc];
__device__ float d_mk[Mm];
__device__ int   d_act[Mm];
__device__ int   d_cnt[Bn];
__device__ float d_psum[2*Bn*Cc];   // zero-init; k_statf re-zeros after use
__device__ float d_mean[Bn*Cc];
__device__ float d_rstd[Bn*Cc];

// ---------------- conv weight restage: coalesced read + tap-major write ------
// rw layout [i][o][c][tap]; dest [cv][tap][o][c] hi/lo fp16.
__global__ void k_wconvr(const float* __restrict__ rw1, const float* __restrict__ rw2){
    __shared__ float sw[4608];                 // 512 (o,c) pairs x 9 taps
    int blk = blockIdx.x;                      // 0..767
    int cv = blk >> 7;                         // 0..5
    int seg = blk & 127;                       // 0..127 (512 oc each)
    int i = cv >> 1;
    const float* rw = (cv & 1) ? rw2 : rw1;
    const float* src = rw + ((size_t)i*65536 + (size_t)seg*512)*9;
    int t = threadIdx.x;
    #pragma unroll
    for (int j = t; j < 1152; j += 256)
        *(float4*)&sw[j*4] = *(const float4*)&src[j*4];
    __syncthreads();
    size_t base = (size_t)cv*9*65536 + (size_t)seg*512;
    #pragma unroll
    for (int tap = 0; tap < 9; tap++){
        int j = 2*t;
        float v0 = sw[j*9 + tap], v1 = sw[(j+1)*9 + tap];
        __half h0,l0,h1,l1; split16(v0,h0,l0); split16(v1,h1,l1);
        size_t d = base + (size_t)tap*65536 + j;
        *(__half2*)&d_wbh[d] = __halves2half2(h0,h1);
        *(__half2*)&d_wbl[d] = __halves2half2(l0,l1);
    }
}
// 1x1 weights (contiguous, simple)
__global__ void k_wconv1(const float* __restrict__ gw, const float* __restrict__ tw,
                         const float* __restrict__ pw, const float* __restrict__ Ww){
    int idx = blockIdx.x*256 + threadIdx.x;    // 0..262143
    int mat = idx >> 16, oc = idx & 65535;
    const float* src = (mat==0) ? gw : (mat==1) ? tw : (mat==2) ? pw : Ww;
    __half h, l; split16(src[oc], h, l);
    d_w1h[idx] = h; d_w1l[idx] = l;
}

// ---------------- x: NCHW -> fp16 hi/lo [B,N,C] ----------------
__global__ void k_xt(const float* __restrict__ x){
    __shared__ float tile[32][33];
    int b = blockIdx.z; int n0 = blockIdx.x*32, c0 = blockIdx.y*32;
    int tx = threadIdx.x, ty = threadIdx.y;
    tile[ty][tx] = x[((size_t)(b*Cc) + c0+ty)*Nn + n0+tx];
    __syncthreads();
    size_t o = ((size_t)(b*Nn) + n0+ty)*Cc + c0+tx;
    __half h, l; split16(tile[tx][ty], h, l);
    d_ah[o] = h; d_al[o] = l;
}

// ---------------- mask + active-key compaction ----------------
__global__ void k_mask(const float* __restrict__ mask){
    int b = blockIdx.x, t = threadIdx.x;
    __shared__ int sc[1024];
    const float* mb = mask + b*32*32;
    int flag[4]; int cnt = 0;
    #pragma unroll
    for (int i=0;i<4;i++){
        int n = t*4+i; int h = n>>6, w = n&63;
        float fy = h*0.5f - 0.25f, fx = w*0.5f - 0.25f;
        int y0 = (int)floorf(fy), x0 = (int)floorf(fx);
        float wy1 = fy - (float)y0, wx1 = fx - (float)x0;
        int y0c = min(max(y0,0),31), y1c = min(max(y0+1,0),31);
        int x0c = min(max(x0,0),31), x1c = min(max(x0+1,0),31);
        float v = (mb[y0c*32+x0c]*(1.f-wx1) + mb[y0c*32+x1c]*wx1)*(1.f-wy1)
                + (mb[y1c*32+x0c]*(1.f-wx1) + mb[y1c*32+x1c]*wx1)*wy1;
        float mv = (v > 0.f) ? 1.f : v;
        float a = 1.f - mv;
        float tmp = 1.f - mb[(h>>1)*32 + (w>>1)];
        float m = a * tmp;
        d_mk[b*Nn + n] = m;
        flag[i] = (m > 0.5f) ? 1 : 0;
        cnt += flag[i];
    }
    sc[t] = cnt; __syncthreads();
    for (int s=1; s<1024; s<<=1){
        int v = (t >= s) ? sc[t-s] : 0;
        __syncthreads();
        sc[t] += v;
        __syncthreads();
    }
    int base = sc[t] - cnt;
    #pragma unroll
    for (int i=0;i<4;i++) if (flag[i]) d_act[b*Nn + (base++)] = t*4+i;
    if (t == 1023) d_cnt[b] = sc[1023];
}

#define PLANE 8192
// ================= 3-term 1x1 GEMM kernel =================
#define STAGE (4*PLANE)           // 32768
#define TM_SMEM_TOTAL (3*STAGE)   // 98304

__device__ __forceinline__ void tmm_load(uint32_t st,
    const __half* __restrict__ Ah, const __half* __restrict__ Al,
    const __half* __restrict__ Wh, const __half* __restrict__ Wl,
    int m0, int n0, int chunk, int t)
{
    int k0 = (chunk & 7)*32;
    #pragma unroll
    for (int it=0; it<2; it++){
        int e = t + it*256;
        int r = e >> 2, ch = e & 3;
        int slot = ch ^ ((r >> 1) & 3);
        uint32_t dst = st + r*64 + (slot << 4);
        size_t srcA = (size_t)(m0 + r)*256 + k0 + ch*8;
        cpasync16(dst,         Ah + srcA);
        cpasync16(dst + PLANE, Al + srcA);
        size_t srcB = ((size_t)(n0 + r))*256 + k0 + ch*8;
        cpasync16(dst + 2*PLANE, Wh + srcB);
        cpasync16(dst + 3*PLANE, Wl + srcB);
    }
}

__global__ void __launch_bounds__(256, 2)
k_tmm(const __half* __restrict__ Ah, const __half* __restrict__ Al,
      const __half* __restrict__ Wh, const __half* __restrict__ Wl,
      const float* __restrict__ bias, float* __restrict__ Cout,
      __half* __restrict__ Oh, __half* __restrict__ Ol)
{
    extern __shared__ char smem[];
    uint32_t sb = smem_u32(smem);
    int t = threadIdx.x, lane = t & 31, wid = t >> 5;
    int warp_m = wid & 3, warp_n = wid >> 2;
    int n0 = blockIdx.x * 128, m0 = blockIdx.y * 128;

    const int S = 8;
    float acc[2][8][4] = {};

    tmm_load(sb,         Ah, Al, Wh, Wl, m0, n0, 0, t);
    asm volatile("cp.async.commit_group;" ::: "memory");
    tmm_load(sb + STAGE, Ah, Al, Wh, Wl, m0, n0, 1, t);
    asm volatile("cp.async.commit_group;" ::: "memory");

    int rA  = warp_m*32 + (lane & 15);
    int hiA = lane >> 4;
    int sxA = (rA >> 1) & 3;
    uint32_t aRow = (uint32_t)rA * 64;
    int rB  = warp_n*64 + (lane & 7) + ((lane >> 4) << 3);
    int gB  = (lane >> 3) & 1;
    int sxB = (rB >> 1) & 3;
    uint32_t bRow = (uint32_t)rB * 64;

    for (int i = 0; i < S; i++){
        int rem = S - 1 - i;
        if (rem >= 1) asm volatile("cp.async.wait_group 1;" ::: "memory");
        else          asm volatile("cp.async.wait_group 0;" ::: "memory");
        __syncthreads();
        if (i + 2 < S){
            tmm_load(sb + (uint32_t)((i+2)%3)*STAGE, Ah, Al, Wh, Wl, m0, n0, i+2, t);
            asm volatile("cp.async.commit_group;" ::: "memory");
        }
        uint32_t st = sb + (uint32_t)(i%3)*STAGE;
        #pragma unroll
        for (int kk = 0; kk < 2; kk++){
            uint32_t aAddr = st + aRow + ((uint32_t)(((2*kk) + hiA) ^ sxA) << 4);
            uint32_t aH[2][4], aL[2][4];
            ldsm4(aH[0], aAddr);
            ldsm4(aH[1], aAddr + 16*64);
            #pragma unroll
            for (int ng = 0; ng < 2; ng++){
                uint32_t bAddr = st + 2*PLANE + bRow + (uint32_t)(ng*32*64)
                               + ((uint32_t)(((2*kk) + gB) ^ sxB) << 4);
                uint32_t bH[8], bL[8];
                ldsm4(*(uint32_t(*)[4])&bH[0], bAddr);
                ldsm4(*(uint32_t(*)[4])&bH[4], bAddr + 16*64);
                #pragma unroll
                for (int j = 0; j < 4; j++){
                    int nt = ng*4 + j;
                    #pragma unroll
                    for (int mt = 0; mt < 2; mt++)
                        mma16816(acc[mt][nt], aH[mt], &bH[2*j]);
                }
                ldsm4(*(uint32_t(*)[4])&bL[0], bAddr + PLANE);
                ldsm4(*(uint32_t(*)[4])&bL[4], bAddr + PLANE + 16*64);
                #pragma unroll
                for (int j = 0; j < 4; j++){
                    int nt = ng*4 + j;
                    #pragma unroll
                    for (int mt = 0; mt < 2; mt++)
                        mma16816(acc[mt][nt], aH[mt], &bL[2*j]);
                }
                if (ng == 0){
                    ldsm4(aL[0], aAddr + PLANE);
                    ldsm4(aL[1], aAddr + PLANE + 16*64);
                }
                #pragma unroll
                for (int j = 0; j < 4; j++){
                    int nt = ng*4 + j;
                    #pragma unroll
                    for (int mt = 0; mt < 2; mt++)
                        mma16816(acc[mt][nt], aL[mt], &bH[2*j]);
                }
            }
        }
    }

    int rbase = m0 + warp_m*32;
    int nb = n0 + warp_n*64;
    int rr = lane >> 2, c2 = 2*(lane & 3);
    #pragma unroll
    for (int mt = 0; mt < 2; mt++){
        #pragma unroll
        for (int nt = 0; nt < 8; nt++){
            int row = rbase + mt*16 + rr;
            int col = nb + nt*8 + c2;
            float b0 = bias[col], b1 = bias[col+1];
            float v00 = acc[mt][nt][0] + b0, v01 = acc[mt][nt][1] + b1;
            float v10 = acc[mt][nt][2] + b0, v11 = acc[mt][nt][3] + b1;
            if (Cout){
                float2 p0; p0.x = v00; p0.y = v01;
                float2 p1; p1.x = v10; p1.y = v11;
                *(float2*)&Cout[(size_t)row*256 + col] = p0;
                *(float2*)&Cout[(size_t)(row+8)*256 + col] = p1;
            }
            if (Oh){
                __half h00, l00, h01, l01, h10, l10, h11, l11;
                split16(v00, h00, l00); split16(v01, h01, l01);
                split16(v10, h10, l10); split16(v11, h11, l11);
                *(__half2*)&Oh[(size_t)row*256 + col]     = __halves2half2(h00, h01);
                *(__half2*)&Oh[(size_t)(row+8)*256 + col] = __halves2half2(h10, h11);
                if (Ol){
                    *(__half2*)&Ol[(size_t)row*256 + col]     = __halves2half2(l00, l01);
                    *(__half2*)&Ol[(size_t)(row+8)*256 + col] = __halves2half2(l10, l11);
                }
            }
        }
    }
}

// ================= 2-term conv kernel: D = Ah @ (Wh + Wl) =================
#define STAGE3 (3*PLANE)            // 24576
#define TC_SMEM_TOTAL (4*STAGE3)    // 98304

__device__ __forceinline__ void tmmc_load(uint32_t st,
    const __half* __restrict__ Ah,
    const __half* __restrict__ Wh, const __half* __restrict__ Wl,
    int m0, int n0, int chunk, int t)
{
    int tap = chunk >> 3, k0 = (chunk & 7)*32;
    int dy = tap/3 - 1, dx = tap%3 - 1;
    #pragma unroll
    for (int it=0; it<2; it++){
        int e = t + it*256;
        int r = e >> 2, ch = e & 3;
        int slot = ch ^ ((r >> 1) & 3);
        uint32_t dst = st + r*64 + (slot << 4);
        int gg = m0 + r, b = gg >> 12, p = gg & 4095, h = p >> 6, w = p & 63;
        int grow = (b << 12) + (refl(h+dy,64) << 6) + refl(w+dx,64);
        cpasync16(dst, Ah + (size_t)grow*256 + k0 + ch*8);
        size_t srcB = ((size_t)tap*256 + n0 + r)*256 + k0 + ch*8;
        cpasync16(dst + PLANE,   Wh + srcB);
        cpasync16(dst + 2*PLANE, Wl + srcB);
    }
}

__global__ void __launch_bounds__(256, 2)
k_tmmc(const __half* __restrict__ Ah,
       const __half* __restrict__ Wh, const __half* __restrict__ Wl,
       const float* __restrict__ bias,
       __half* __restrict__ Oh, __half* __restrict__ Ol,
       float* __restrict__ psum)
{
    extern __shared__ char smem[];
    uint32_t sb = smem_u32(smem);
    int t = threadIdx.x, lane = t & 31, wid = t >> 5;
    int warp_m = wid & 3, warp_n = wid >> 2;
    int n0 = blockIdx.x * 128, m0 = blockIdx.y * 128;

    const int S = 72;
    float acc[2][8][4] = {};

    tmmc_load(sb,          Ah, Wh, Wl, m0, n0, 0, t);
    tmmc_load(sb + STAGE3, Ah, Wh, Wl, m0, n0, 1, t);
    asm volatile("cp.async.commit_group;" ::: "memory");

    int rA  = warp_m*32 + (lane & 15);
    int hiA = lane >> 4;
    int sxA = (rA >> 1) & 3;
    uint32_t aRow = (uint32_t)rA * 64;
    int rB  = warp_n*64 + (lane & 7) + ((lane >> 4) << 3);
    int gB  = (lane >> 3) & 1;
    int sxB = (rB >> 1) & 3;
    uint32_t bRow = (uint32_t)rB * 64;

    for (int p = 0; p < S/2; p++){
        asm volatile("cp.async.wait_group 0;" ::: "memory");
        __syncthreads();
        if (2*p + 2 < S){
            tmmc_load(sb + (uint32_t)((2*p+2)&3)*STAGE3, Ah, Wh, Wl, m0, n0, 2*p+2, t);
            tmmc_load(sb + (uint32_t)((2*p+3)&3)*STAGE3, Ah, Wh, Wl, m0, n0, 2*p+3, t);
            asm volatile("cp.async.commit_group;" ::: "memory");
        }
        #pragma unroll
        for (int q = 0; q < 2; q++){
            uint32_t st = sb + (uint32_t)((2*p+q)&3)*STAGE3;
            #pragma unroll
            for (int kk = 0; kk < 2; kk++){
                uint32_t aAddr = st + aRow + ((uint32_t)(((2*kk) + hiA) ^ sxA) << 4);
                uint32_t aH[2][4];
                ldsm4(aH[0], aAddr);
                ldsm4(aH[1], aAddr + 16*64);
                #pragma unroll
                for (int ng = 0; ng < 2; ng++){
                    uint32_t bAddr = st + PLANE + bRow + (uint32_t)(ng*32*64)
                                   + ((uint32_t)(((2*kk) + gB) ^ sxB) << 4);
                    uint32_t bH[8], bL[8];
                    ldsm4(*(uint32_t(*)[4])&bH[0], bAddr);
                    ldsm4(*(uint32_t(*)[4])&bH[4], bAddr + 16*64);
                    #pragma unroll
                    for (int j = 0; j < 4; j++){
                        int nt = ng*4 + j;
                        #pragma unroll
                        for (int mt = 0; mt < 2; mt++)
                            mma16816(acc[mt][nt], aH[mt], &bH[2*j]);
                    }
                    ldsm4(*(uint32_t(*)[4])&bL[0], bAddr + PLANE);
                    ldsm4(*(uint32_t(*)[4])&bL[4], bAddr + PLANE + 16*64);
                    #pragma unroll
                    for (int j = 0; j < 4; j++){
                        int nt = ng*4 + j;
                        #pragma unroll
                        for (int mt = 0; mt < 2; mt++)
                            mma16816(acc[mt][nt], aH[mt], &bL[2*j]);
                    }
                }
            }
        }
    }

    // ---- epilogue: planes + fused IN stats ----
    int rbase = m0 + warp_m*32;
    int nb = n0 + warp_n*64;
    int rr = lane >> 2, c2 = 2*(lane & 3);
    float cs[16] = {}, cs2[16] = {};
    #pragma unroll
    for (int mt = 0; mt < 2; mt++){
        #pragma unroll
        for (int nt = 0; nt < 8; nt++){
            int row = rbase + mt*16 + rr;
            int col = nb + nt*8 + c2;
            float b0 = bias[col], b1 = bias[col+1];
            float v00 = acc[mt][nt][0] + b0, v01 = acc[mt][nt][1] + b1;
            float v10 = acc[mt][nt][2] + b0, v11 = acc[mt][nt][3] + b1;
            __half h00, l00, h01, l01, h10, l10, h11, l11;
            split16(v00, h00, l00); split16(v01, h01, l01);
            split16(v10, h10, l10); split16(v11, h11, l11);
            *(__half2*)&Oh[(size_t)row*256 + col]     = __halves2half2(h00, h01);
            *(__half2*)&Ol[(size_t)row*256 + col]     = __halves2half2(l00, l01);
            *(__half2*)&Oh[(size_t)(row+8)*256 + col] = __halves2half2(h10, h11);
            *(__half2*)&Ol[(size_t)(row+8)*256 + col] = __halves2half2(l10, l11);
            cs [nt*2]   += v00 + v10;
            cs [nt*2+1] += v01 + v11;
            cs2[nt*2]   += v00*v00 + v10*v10;
            cs2[nt*2+1] += v01*v01 + v11*v11;
        }
    }
    #pragma unroll
    for (int o = 4; o <= 16; o <<= 1){
        #pragma unroll
        for (int j = 0; j < 16; j++){
            cs[j]  += __shfl_xor_sync(0xffffffffu, cs[j],  o);
            cs2[j] += __shfl_xor_sync(0xffffffffu, cs2[j], o);
        }
    }
    if (lane < 4){
        int b = m0 >> 12;
        #pragma unroll
        for (int nt = 0; nt < 8; nt++){
            int col = nb + nt*8 + 2*lane;
            atomicAdd(&psum[b*256 + col],          cs [2*nt]);
            atomicAdd(&psum[b*256 + col + 1],      cs [2*nt+1]);
            atomicAdd(&psum[1024 + b*256 + col],   cs2[2*nt]);
            atomicAdd(&psum[1024 + b*256 + col+1], cs2[2*nt+1]);
        }
    }
}

// ---------------- masked-softmax attention over compacted keys ----------------
__global__ void __launch_bounds__(256) k_attn(){
    int b = blockIdx.y; int q0 = blockIdx.x * 16;
    __shared__ float Qs[16][260];
    __shared__ float Ks[16][260];
    __shared__ float Gs[16][260];
    __shared__ float Ss[16][17];
    int t = threadIdx.x;
    for (int i4 = t; i4 < 16*64; i4 += 256){
        int r = i4 >> 6, c4 = (i4 & 63) * 4;
        *(float4*)&Qs[r][c4] = *(const float4*)&d_q[((size_t)(b*Nn) + q0 + r)*256 + c4];
    }
    int cnt = d_cnt[b];
    int q = t >> 4, lane = t & 15;
    float yacc[16];
    #pragma unroll
    for (int i=0;i<16;i++) yacc[i] = 0.f;
    float rmax = -1e30f, rsum = 0.f;
    __syncthreads();
    for (int j0=0; j0<cnt; j0+=16){
        int jn = min(16, cnt - j0);
        for (int i4 = t; i4 < jn*64; i4 += 256){
            int r = i4 >> 6, c4 = (i4 & 63) * 4;
            int src = d_act[b*Nn + j0 + r];
            *(float4*)&Ks[r][c4] = *(const float4*)&d_kk[((size_t)(b*Nn) + src)*256 + c4];
            *(float4*)&Gs[r][c4] = *(const float4*)&d_gg[((size_t)(b*Nn) + src)*256 + c4];
        }
        __syncthreads();
        float s = -1e30f;
        if (lane < jn){
            s = 0.f;
            #pragma unroll 4
            for (int c4 = 0; c4 < 64; c4++){
                float4 qv = *(const float4*)&Qs[q][c4*4];
                float4 kv = *(const float4*)&Ks[lane][c4*4];
                s += qv.x*kv.x + qv.y*kv.y + qv.z*kv.z + qv.w*kv.w;
            }
        }
        Ss[q][lane] = s;
        __syncthreads();
        float cmax = rmax;
        for (int j=0;j<jn;j++) cmax = fmaxf(cmax, Ss[q][j]);
        float scale = __expf(rmax - cmax);
        rsum *= scale;
        #pragma unroll
        for (int i=0;i<16;i++) yacc[i] *= scale;
        for (int j=0;j<jn;j++){
            float pj = __expf(Ss[q][j] - cmax);
            rsum += pj;
            #pragma unroll
            for (int i=0;i<16;i++) yacc[i] += pj * Gs[j][lane + i*16];
        }
        rmax = cmax;
        __syncthreads();
    }
    float inv = (rsum > 0.f) ? (1.f/rsum) : 0.f;
    #pragma unroll
    for (int i=0;i<16;i++){
        float v = yacc[i]*inv;
        size_t o = ((size_t)(b*Nn) + q0 + q)*256 + lane + i*16;
        __half h, l; split16(v, h, l);
        d_ph[o] = h; d_pl[o] = l;
    }
}

// ---------------- instance-norm finalize (reads+zeros psum) ----------------
__global__ void k_statf(){
    int b = blockIdx.x, c = threadIdx.x;
    float s  = d_psum[b*256 + c];
    float s2 = d_psum[1024 + b*256 + c];
    float mu = s * (1.f/4096.f);
    float var = s2 * (1.f/4096.f) - mu*mu;
    d_mean[b*256+c] = mu;
    d_rstd[b*256+c] = rsqrtf(var + 1e-5f);
    d_psum[b*256 + c] = 0.f;
    d_psum[1024 + b*256 + c] = 0.f;
}

// relu(IN(t-planes)) -> p-hi plane only (consumer conv is 2-term)
__global__ void k_in_relu(){
    int i2 = blockIdx.x*256 + threadIdx.x;
    int base = i2*2;
    int c = base & 255; int b = base >> 20;
    __half2 h2 = *(const __half2*)&d_th[base];
    __half2 l2 = *(const __half2*)&d_tl[base];
    float v0 = __half2float(h2.x) + __half2float(l2.x);
    float v1 = __half2float(h2.y) + __half2float(l2.y);
    v0 = fmaxf((v0 - d_mean[b*256+c])   * d_rstd[b*256+c],   0.f);
    v1 = fmaxf((v1 - d_mean[b*256+c+1]) * d_rstd[b*256+c+1], 0.f);
    *(__half2*)&d_ph[base] = __halves2half2(__float2half(v0), __float2half(v1));
}
// wyh += IN(t-planes), stored fp16
__global__ void k_in_add(){
    int i2 = blockIdx.x*256 + threadIdx.x;
    int base = i2*2;
    int c = base & 255; int b = base >> 20;
    __half2 h2 = *(const __half2*)&d_th[base];
    __half2 l2 = *(const __half2*)&d_tl[base];
    float v0 = __half2float(h2.x) + __half2float(l2.x);
    float v1 = __half2float(h2.y) + __half2float(l2.y);
    __half2 w2 = *(const __half2*)&d_wyh[base];
    float w0 = __half2float(w2.x) + (v0 - d_mean[b*256+c])   * d_rstd[b*256+c];
    float w1 = __half2float(w2.y) + (v1 - d_mean[b*256+c+1]) * d_rstd[b*256+c+1];
    *(__half2*)&d_wyh[base] = __halves2half2(__float2half(w0), __float2half(w1));
}

// ---------------- final blend + NHWC->NCHW ----------------
__global__ void k_blend(const float* __restrict__ x, float* __restrict__ z){
    __shared__ float tile[32][33];
    int b = blockIdx.z; int n0 = blockIdx.x*32, c0 = blockIdx.y*32;
    int tx = threadIdx.x, ty = threadIdx.y;
    tile[ty][tx] = __half2float(d_wyh[((size_t)(b*Nn) + n0+ty)*256 + c0+tx]);
    __syncthreads();
    int n = n0 + tx, c = c0 + ty;
    float m = d_mk[b*Nn + n];
    size_t idx = ((size_t)(b*Cc + c))*Nn + n;
    z[idx] = m * x[idx] + (1.f - m) * tile[tx][ty];
}

// ---------------- launch ----------------
extern "C" void kernel_launch(void* const* d_in, const int* in_sizes, int n_in,
                              void* d_out, int out_size) {
    (void)in_sizes; (void)n_in; (void)out_size;
    const float* x    = (const float*)d_in[0];
    const float* mask = (const float*)d_in[1];
    const float* g_w  = (const float*)d_in[2];
    const float* g_b  = (const float*)d_in[3];
    const float* th_w = (const float*)d_in[4];
    const float* th_b = (const float*)d_in[5];
    const float* ph_w = (const float*)d_in[6];
    const float* ph_b = (const float*)d_in[7];
    const float* W_w  = (const float*)d_in[8];
    const float* W_b  = (const float*)d_in[9];
    const float* rw1  = (const float*)d_in[10];
    const float* rb1  = (const float*)d_in[11];
    const float* rw2  = (const float*)d_in[12];
    const float* rb2  = (const float*)d_in[13];
    float* z = (float*)d_out;

    cudaFuncSetAttribute(k_tmm,  cudaFuncAttributeMaxDynamicSharedMemorySize, TM_SMEM_TOTAL);
    cudaFuncSetAttribute(k_tmmc, cudaFuncAttributeMaxDynamicSharedMemorySize, TC_SMEM_TOTAL);

    float *pq, *pk, *pg, *pps;
    __half *pwyh, *pah, *pal, *pph, *ppl, *pth, *ptl, *pwbh, *pwbl, *pw1h, *pw1l;
    cudaGetSymbolAddress((void**)&pq,  d_q);
    cudaGetSymbolAddress((void**)&pk,  d_kk);
    cudaGetSymbolAddress((void**)&pg,  d_gg);
    cudaGetSymbolAddress((void**)&pps, d_psum);
    cudaGetSymbolAddress((void**)&pwyh, d_wyh);
    cudaGetSymbolAddress((void**)&pah, d_ah);
    cudaGetSymbolAddress((void**)&pal, d_al);
    cudaGetSymbolAddress((void**)&pph, d_ph);
    cudaGetSymbolAddress((void**)&ppl, d_pl);
    cudaGetSymbolAddress((void**)&pth, d_th);
    cudaGetSymbolAddress((void**)&ptl, d_tl);
    cudaGetSymbolAddress((void**)&pwbh, d_wbh);
    cudaGetSymbolAddress((void**)&pwbl, d_wbl);
    cudaGetSymbolAddress((void**)&pw1h, d_w1h);
    cudaGetSymbolAddress((void**)&pw1l, d_w1l);

    dim3 t32(32,32);
    k_wconvr<<<768, 256>>>(rw1, rw2);
    k_wconv1<<<1024, 256>>>(g_w, th_w, ph_w, W_w);
    k_xt  <<<dim3(128,8,4), t32>>>(x);
    k_mask<<<4, 1024>>>(mask);

    dim3 gg(2,128);
    k_tmm<<<gg,256,TM_SMEM_TOTAL>>>(pah, pal, pw1h+1*65536, pw1l+1*65536, th_b, pq, 0, 0);
    k_tmm<<<gg,256,TM_SMEM_TOTAL>>>(pah, pal, pw1h+2*65536, pw1l+2*65536, ph_b, pk, 0, 0);
    k_tmm<<<gg,256,TM_SMEM_TOTAL>>>(pah, pal, pw1h+0*65536, pw1l+0*65536, g_b,  pg, 0, 0);

    k_attn<<<dim3(256,4),256>>>();   // -> p-planes (hi+lo)

    // W 1x1: p-planes -> wyh (fp16 residual stream)
    k_tmm<<<gg,256,TM_SMEM_TOTAL>>>(pph, ppl, pw1h+3*65536, pw1l+3*65536, W_b, 0, pwyh, 0);

    for (int i=0;i<3;i++){
        k_tmmc<<<gg,256,TC_SMEM_TOTAL>>>(pwyh, pwbh + (size_t)(2*i)*9*65536,
                                         pwbl + (size_t)(2*i)*9*65536, rb1 + i*256,
                                         pth, ptl, pps);
        k_statf<<<4,256>>>();
        k_in_relu<<<8192,256>>>();
        k_tmmc<<<gg,256,TC_SMEM_TOTAL>>>(pph, pwbh + (size_t)(2*i+1)*9*65536,
                                         pwbl + (size_t)(2*i+1)*9*65536, rb2 + i*256,
                                         pth, ptl, pps);
        k_statf<<<4,256>>>();
        k_in_add<<<8192,256>>>();
    }

    k_blend<<<dim3(128,8,4), t32>>>(x, z);
}

// round 17
// speedup vs baseline: 2.7370x; 1.0220x over previous
#include <cuda_runtime.h>
#include <cuda_fp16.h>
#include <math.h>
#include <stdint.h>

#define Bn 4
#define Cc 256
#define Nn 4096
#define Mm (Bn*Nn)   // 16384

// ---------------- helpers ----------------
__device__ __forceinline__ uint32_t smem_u32(const void* p){
    uint32_t a;
    asm("{ .reg .u64 t; cvta.to.shared.u64 t, %1; cvt.u32.u64 %0, t; }" : "=r"(a) : "l"(p));
    return a;
}
__device__ __forceinline__ int refl(int i, int n){ return i<0 ? -i : (i>=n ? 2*n-2-i : i); }

__device__ __forceinline__ void cpasync16(uint32_t dst, const void* src){
    asm volatile("cp.async.cg.shared.global [%0], [%1], 16;" :: "r"(dst), "l"(src) : "memory");
}
__device__ __forceinline__ void ldsm4(uint32_t (&r)[4], uint32_t addr){
    asm volatile("ldmatrix.sync.aligned.m8n8.x4.shared.b16 {%0,%1,%2,%3}, [%4];"
        : "=r"(r[0]), "=r"(r[1]), "=r"(r[2]), "=r"(r[3]) : "r"(addr));
}
__device__ __forceinline__ void mma16816(float (&d)[4], const uint32_t (&a)[4], const uint32_t* b){
    asm volatile("mma.sync.aligned.m16n8k16.row.col.f32.f16.f16.f32 "
        "{%0,%1,%2,%3},{%4,%5,%6,%7},{%8,%9},{%0,%1,%2,%3};"
        : "+f"(d[0]), "+f"(d[1]), "+f"(d[2]), "+f"(d[3])
        : "r"(a[0]), "r"(a[1]), "r"(a[2]), "r"(a[3]), "r"(b[0]), "r"(b[1]));
}
__device__ __forceinline__ void split16(float v, __half &h, __half &l){
    h = __float2half(v);
    l = __float2half(v - __half2float(h));
}

// ---------------- scratch (device globals) ----------------
__device__ __half d_qh[Mm*Cc];   // theta rows (fp16)
__device__ __half d_kh[Mm*Cc];   // phi rows
__device__ __half d_gh[Mm*Cc];   // g rows
__device__ __half d_wyh[Mm*Cc];  // residual stream (fp16)
__device__ __half d_ah[Mm*Cc];   // x planes (QKG input, hi/lo)
__device__ __half d_al[Mm*Cc];
__device__ __half d_ph[Mm*Cc];   // post-relu / attention-out plane
__device__ __half d_th[Mm*Cc];   // conv output planes (pre-IN)
__device__ __half d_tl[Mm*Cc];
__device__ __half d_wbh[6*9*Cc*Cc];
__device__ __half d_wbl[6*9*Cc*Cc];
__device__ __half d_w1h[4*Cc*Cc];
__device__ __half d_w1l[4*Cc*Cc];
__device__ float d_mk[Mm];
__device__ int   d_act[Mm];
__device__ int   d_cnt[Bn];
__device__ float d_psum[2*Bn*Cc];   // zero-init; k_statf re-zeros after use
__device__ float d_mean[Bn*Cc];
__device__ float d_rstd[Bn*Cc];

// ---------------- conv weight restage: coalesced read + tap-major write ------
__global__ void k_wconvr(const float* __restrict__ rw1, const float* __restrict__ rw2){
    __shared__ float sw[4608];
    int blk = blockIdx.x;                      // 0..767
    int cv = blk >> 7;
    int seg = blk & 127;
    int i = cv >> 1;
    const float* rw = (cv & 1) ? rw2 : rw1;
    const float* src = rw + ((size_t)i*65536 + (size_t)seg*512)*9;
    int t = threadIdx.x;
    #pragma unroll
    for (int j = t; j < 1152; j += 256)
        *(float4*)&sw[j*4] = *(const float4*)&src[j*4];
    __syncthreads();
    size_t base = (size_t)cv*9*65536 + (size_t)seg*512;
    #pragma unroll
    for (int tap = 0; tap < 9; tap++){
        int j = 2*t;
        float v0 = sw[j*9 + tap], v1 = sw[(j+1)*9 + tap];
        __half h0,l0,h1,l1; split16(v0,h0,l0); split16(v1,h1,l1);
        size_t d = base + (size_t)tap*65536 + j;
        *(__half2*)&d_wbh[d] = __halves2half2(h0,h1);
        *(__half2*)&d_wbl[d] = __halves2half2(l0,l1);
    }
}
__global__ void k_wconv1(const float* __restrict__ gw, const float* __restrict__ tw,
                         const float* __restrict__ pw, const float* __restrict__ Ww){
    int idx = blockIdx.x*256 + threadIdx.x;
    int mat = idx >> 16, oc = idx & 65535;
    const float* src = (mat==0) ? gw : (mat==1) ? tw : (mat==2) ? pw : Ww;
    __half h, l; split16(src[oc], h, l);
    d_w1h[idx] = h; d_w1l[idx] = l;
}

// ---------------- x: NCHW -> fp16 hi/lo [B,N,C] ----------------
__global__ void k_xt(const float* __restrict__ x){
    __shared__ float tile[32][33];
    int b = blockIdx.z; int n0 = blockIdx.x*32, c0 = blockIdx.y*32;
    int tx = threadIdx.x, ty = threadIdx.y;
    tile[ty][tx] = x[((size_t)(b*Cc) + c0+ty)*Nn + n0+tx];
    __syncthreads();
    size_t o = ((size_t)(b*Nn) + n0+ty)*Cc + c0+tx;
    __half h, l; split16(tile[tx][ty], h, l);
    d_ah[o] = h; d_al[o] = l;
}

// ---------------- mask + active-key compaction ----------------
__global__ void k_mask(const float* __restrict__ mask){
    int b = blockIdx.x, t = threadIdx.x;
    __shared__ int sc[1024];
    const float* mb = mask + b*32*32;
    int flag[4]; int cnt = 0;
    #pragma unroll
    for (int i=0;i<4;i++){
        int n = t*4+i; int h = n>>6, w = n&63;
        float fy = h*0.5f - 0.25f, fx = w*0.5f - 0.25f;
        int y0 = (int)floorf(fy), x0 = (int)floorf(fx);
        float wy1 = fy - (float)y0, wx1 = fx - (float)x0;
        int y0c = min(max(y0,0),31), y1c = min(max(y0+1,0),31);
        int x0c = min(max(x0,0),31), x1c = min(max(x0+1,0),31);
        float v = (mb[y0c*32+x0c]*(1.f-wx1) + mb[y0c*32+x1c]*wx1)*(1.f-wy1)
                + (mb[y1c*32+x0c]*(1.f-wx1) + mb[y1c*32+x1c]*wx1)*wy1;
        float mv = (v > 0.f) ? 1.f : v;
        float a = 1.f - mv;
        float tmp = 1.f - mb[(h>>1)*32 + (w>>1)];
        float m = a * tmp;
        d_mk[b*Nn + n] = m;
        flag[i] = (m > 0.5f) ? 1 : 0;
        cnt += flag[i];
    }
    sc[t] = cnt; __syncthreads();
    for (int s=1; s<1024; s<<=1){
        int v = (t >= s) ? sc[t-s] : 0;
        __syncthreads();
        sc[t] += v;
        __syncthreads();
    }
    int base = sc[t] - cnt;
    #pragma unroll
    for (int i=0;i<4;i++) if (flag[i]) d_act[b*Nn + (base++)] = t*4+i;
    if (t == 1023) d_cnt[b] = sc[1023];
}

#define PLANE 8192
// ================= 3-term 1x1 GEMM kernel (QKG; x hi/lo input) =================
#define STAGE (4*PLANE)           // 32768
#define TM_SMEM_TOTAL (3*STAGE)   // 98304

__device__ __forceinline__ void tmm_load(uint32_t st,
    const __half* __restrict__ Ah, const __half* __restrict__ Al,
    const __half* __restrict__ Wh, const __half* __restrict__ Wl,
    int m0, int n0, int chunk, int t)
{
    int k0 = (chunk & 7)*32;
    #pragma unroll
    for (int it=0; it<2; it++){
        int e = t + it*256;
        int r = e >> 2, ch = e & 3;
        int slot = ch ^ ((r >> 1) & 3);
        uint32_t dst = st + r*64 + (slot << 4);
        size_t srcA = (size_t)(m0 + r)*256 + k0 + ch*8;
        cpasync16(dst,         Ah + srcA);
        cpasync16(dst + PLANE, Al + srcA);
        size_t srcB = ((size_t)(n0 + r))*256 + k0 + ch*8;
        cpasync16(dst + 2*PLANE, Wh + srcB);
        cpasync16(dst + 3*PLANE, Wl + srcB);
    }
}

__global__ void __launch_bounds__(256, 2)
k_tmm(const __half* __restrict__ Ah, const __half* __restrict__ Al,
      const __half* __restrict__ Wh, const __half* __restrict__ Wl,
      const float* __restrict__ bias, __half* __restrict__ Oh)
{
    extern __shared__ char smem[];
    uint32_t sb = smem_u32(smem);
    int t = threadIdx.x, lane = t & 31, wid = t >> 5;
    int warp_m = wid & 3, warp_n = wid >> 2;
    int n0 = blockIdx.x * 128, m0 = blockIdx.y * 128;

    const int S = 8;
    float acc[2][8][4] = {};

    tmm_load(sb,         Ah, Al, Wh, Wl, m0, n0, 0, t);
    asm volatile("cp.async.commit_group;" ::: "memory");
    tmm_load(sb + STAGE, Ah, Al, Wh, Wl, m0, n0, 1, t);
    asm volatile("cp.async.commit_group;" ::: "memory");

    int rA  = warp_m*32 + (lane & 15);
    int hiA = lane >> 4;
    int sxA = (rA >> 1) & 3;
    uint32_t aRow = (uint32_t)rA * 64;
    int rB  = warp_n*64 + (lane & 7) + ((lane >> 4) << 3);
    int gB  = (lane >> 3) & 1;
    int sxB = (rB >> 1) & 3;
    uint32_t bRow = (uint32_t)rB * 64;

    for (int i = 0; i < S; i++){
        int rem = S - 1 - i;
        if (rem >= 1) asm volatile("cp.async.wait_group 1;" ::: "memory");
        else          asm volatile("cp.async.wait_group 0;" ::: "memory");
        __syncthreads();
        if (i + 2 < S){
            tmm_load(sb + (uint32_t)((i+2)%3)*STAGE, Ah, Al, Wh, Wl, m0, n0, i+2, t);
            asm volatile("cp.async.commit_group;" ::: "memory");
        }
        uint32_t st = sb + (uint32_t)(i%3)*STAGE;
        #pragma unroll
        for (int kk = 0; kk < 2; kk++){
            uint32_t aAddr = st + aRow + ((uint32_t)(((2*kk) + hiA) ^ sxA) << 4);
            uint32_t aH[2][4], aL[2][4];
            ldsm4(aH[0], aAddr);
            ldsm4(aH[1], aAddr + 16*64);
            #pragma unroll
            for (int ng = 0; ng < 2; ng++){
                uint32_t bAddr = st + 2*PLANE + bRow + (uint32_t)(ng*32*64)
                               + ((uint32_t)(((2*kk) + gB) ^ sxB) << 4);
                uint32_t bH[8], bL[8];
                ldsm4(*(uint32_t(*)[4])&bH[0], bAddr);
                ldsm4(*(uint32_t(*)[4])&bH[4], bAddr + 16*64);
                #pragma unroll
                for (int j = 0; j < 4; j++){
                    int nt = ng*4 + j;
                    #pragma unroll
                    for (int mt = 0; mt < 2; mt++)
                        mma16816(acc[mt][nt], aH[mt], &bH[2*j]);
                }
                ldsm4(*(uint32_t(*)[4])&bL[0], bAddr + PLANE);
                ldsm4(*(uint32_t(*)[4])&bL[4], bAddr + PLANE + 16*64);
                #pragma unroll
                for (int j = 0; j < 4; j++){
                    int nt = ng*4 + j;
                    #pragma unroll
                    for (int mt = 0; mt < 2; mt++)
                        mma16816(acc[mt][nt], aH[mt], &bL[2*j]);
                }
                if (ng == 0){
                    ldsm4(aL[0], aAddr + PLANE);
                    ldsm4(aL[1], aAddr + PLANE + 16*64);
                }
                #pragma unroll
                for (int j = 0; j < 4; j++){
                    int nt = ng*4 + j;
                    #pragma unroll
                    for (int mt = 0; mt < 2; mt++)
                        mma16816(acc[mt][nt], aL[mt], &bH[2*j]);
                }
            }
        }
    }

    int rbase = m0 + warp_m*32;
    int nb = n0 + warp_n*64;
    int rr = lane >> 2, c2 = 2*(lane & 3);
    #pragma unroll
    for (int mt = 0; mt < 2; mt++){
        #pragma unroll
        for (int nt = 0; nt < 8; nt++){
            int row = rbase + mt*16 + rr;
            int col = nb + nt*8 + c2;
            float b0 = bias[col], b1 = bias[col+1];
            float v00 = acc[mt][nt][0] + b0, v01 = acc[mt][nt][1] + b1;
            float v10 = acc[mt][nt][2] + b0, v11 = acc[mt][nt][3] + b1;
            *(__half2*)&Oh[(size_t)row*256 + col] =
                __halves2half2(__float2half(v00), __float2half(v01));
            *(__half2*)&Oh[(size_t)(row+8)*256 + col] =
                __halves2half2(__float2half(v10), __float2half(v11));
        }
    }
}

// ================= 2-term kernel: D = Ah @ (Wh + Wl) (conv + W-1x1) =========
#define STAGE3 (3*PLANE)            // 24576
#define TC_SMEM_TOTAL (4*STAGE3)    // 98304

__device__ __forceinline__ void tmmc_load(uint32_t st,
    const __half* __restrict__ Ah,
    const __half* __restrict__ Wh, const __half* __restrict__ Wl,
    int m0, int n0, int chunk, int ntaps, int t)
{
    int tap = chunk >> 3, k0 = (chunk & 7)*32;
    int dy = tap/3 - 1, dx = tap%3 - 1;
    #pragma unroll
    for (int it=0; it<2; it++){
        int e = t + it*256;
        int r = e >> 2, ch = e & 3;
        int slot = ch ^ ((r >> 1) & 3);
        uint32_t dst = st + r*64 + (slot << 4);
        int grow;
        if (ntaps > 1){
            int gg = m0 + r, b = gg >> 12, p = gg & 4095, h = p >> 6, w = p & 63;
            grow = (b << 12) + (refl(h+dy,64) << 6) + refl(w+dx,64);
        } else grow = m0 + r;
        cpasync16(dst, Ah + (size_t)grow*256 + k0 + ch*8);
        size_t srcB = ((size_t)tap*256 + n0 + r)*256 + k0 + ch*8;
        cpasync16(dst + PLANE,   Wh + srcB);
        cpasync16(dst + 2*PLANE, Wl + srcB);
    }
}

__global__ void __launch_bounds__(256, 2)
k_tmmc(const __half* __restrict__ Ah,
       const __half* __restrict__ Wh, const __half* __restrict__ Wl,
       const float* __restrict__ bias,
       __half* __restrict__ Oh, __half* __restrict__ Ol,
       float* __restrict__ psum, int ntaps)
{
    extern __shared__ char smem[];
    uint32_t sb = smem_u32(smem);
    int t = threadIdx.x, lane = t & 31, wid = t >> 5;
    int warp_m = wid & 3, warp_n = wid >> 2;
    int n0 = blockIdx.x * 128, m0 = blockIdx.y * 128;

    int S = ntaps * 8;
    float acc[2][8][4] = {};

    tmmc_load(sb,          Ah, Wh, Wl, m0, n0, 0, ntaps, t);
    tmmc_load(sb + STAGE3, Ah, Wh, Wl, m0, n0, 1, ntaps, t);
    asm volatile("cp.async.commit_group;" ::: "memory");

    int rA  = warp_m*32 + (lane & 15);
    int hiA = lane >> 4;
    int sxA = (rA >> 1) & 3;
    uint32_t aRow = (uint32_t)rA * 64;
    int rB  = warp_n*64 + (lane & 7) + ((lane >> 4) << 3);
    int gB  = (lane >> 3) & 1;
    int sxB = (rB >> 1) & 3;
    uint32_t bRow = (uint32_t)rB * 64;

    for (int p = 0; p < S/2; p++){
        asm volatile("cp.async.wait_group 0;" ::: "memory");
        __syncthreads();
        if (2*p + 2 < S){
            tmmc_load(sb + (uint32_t)((2*p+2)&3)*STAGE3, Ah, Wh, Wl, m0, n0, 2*p+2, ntaps, t);
            tmmc_load(sb + (uint32_t)((2*p+3)&3)*STAGE3, Ah, Wh, Wl, m0, n0, 2*p+3, ntaps, t);
            asm volatile("cp.async.commit_group;" ::: "memory");
        }
        #pragma unroll
        for (int q = 0; q < 2; q++){
            uint32_t st = sb + (uint32_t)((2*p+q)&3)*STAGE3;
            #pragma unroll
            for (int kk = 0; kk < 2; kk++){
                uint32_t aAddr = st + aRow + ((uint32_t)(((2*kk) + hiA) ^ sxA) << 4);
                uint32_t aH[2][4];
                ldsm4(aH[0], aAddr);
                ldsm4(aH[1], aAddr + 16*64);
                #pragma unroll
                for (int ng = 0; ng < 2; ng++){
                    uint32_t bAddr = st + PLANE + bRow + (uint32_t)(ng*32*64)
                                   + ((uint32_t)(((2*kk) + gB) ^ sxB) << 4);
                    uint32_t bH[8], bL[8];
                    ldsm4(*(uint32_t(*)[4])&bH[0], bAddr);
                    ldsm4(*(uint32_t(*)[4])&bH[4], bAddr + 16*64);
                    #pragma unroll
                    for (int j = 0; j < 4; j++){
                        int nt = ng*4 + j;
                        #pragma unroll
                        for (int mt = 0; mt < 2; mt++)
                            mma16816(acc[mt][nt], aH[mt], &bH[2*j]);
                    }
                    ldsm4(*(uint32_t(*)[4])&bL[0], bAddr + PLANE);
                    ldsm4(*(uint32_t(*)[4])&bL[4], bAddr + PLANE + 16*64);
                    #pragma unroll
                    for (int j = 0; j < 4; j++){
                        int nt = ng*4 + j;
                        #pragma unroll
                        for (int mt = 0; mt < 2; mt++)
                            mma16816(acc[mt][nt], aH[mt], &bL[2*j]);
                    }
                }
            }
        }
    }

    // ---- epilogue: planes + optional fused IN stats ----
    int rbase = m0 + warp_m*32;
    int nb = n0 + warp_n*64;
    int rr = lane >> 2, c2 = 2*(lane & 3);
    float cs[16] = {}, cs2[16] = {};
    #pragma unroll
    for (int mt = 0; mt < 2; mt++){
        #pragma unroll
        for (int nt = 0; nt < 8; nt++){
            int row = rbase + mt*16 + rr;
            int col = nb + nt*8 + c2;
            float b0 = bias[col], b1 = bias[col+1];
            float v00 = acc[mt][nt][0] + b0, v01 = acc[mt][nt][1] + b1;
            float v10 = acc[mt][nt][2] + b0, v11 = acc[mt][nt][3] + b1;
            __half h00, l00, h01, l01, h10, l10, h11, l11;
            split16(v00, h00, l00); split16(v01, h01, l01);
            split16(v10, h10, l10); split16(v11, h11, l11);
            *(__half2*)&Oh[(size_t)row*256 + col]     = __halves2half2(h00, h01);
            *(__half2*)&Oh[(size_t)(row+8)*256 + col] = __halves2half2(h10, h11);
            if (Ol){
                *(__half2*)&Ol[(size_t)row*256 + col]     = __halves2half2(l00, l01);
                *(__half2*)&Ol[(size_t)(row+8)*256 + col] = __halves2half2(l10, l11);
            }
            cs [nt*2]   += v00 + v10;
            cs [nt*2+1] += v01 + v11;
            cs2[nt*2]   += v00*v00 + v10*v10;
            cs2[nt*2+1] += v01*v01 + v11*v11;
        }
    }
    if (psum){
        #pragma unroll
        for (int o = 4; o <= 16; o <<= 1){
            #pragma unroll
            for (int j = 0; j < 16; j++){
                cs[j]  += __shfl_xor_sync(0xffffffffu, cs[j],  o);
                cs2[j] += __shfl_xor_sync(0xffffffffu, cs2[j], o);
            }
        }
        if (lane < 4){
            int b = m0 >> 12;
            #pragma unroll
            for (int nt = 0; nt < 8; nt++){
                int col = nb + nt*8 + 2*lane;
                atomicAdd(&psum[b*256 + col],          cs [2*nt]);
                atomicAdd(&psum[b*256 + col + 1],      cs [2*nt+1]);
                atomicAdd(&psum[1024 + b*256 + col],   cs2[2*nt]);
                atomicAdd(&psum[1024 + b*256 + col+1], cs2[2*nt+1]);
            }
        }
    }
}

// ---------------- masked-softmax attention (fp16 smem, fp32 softmax) ---------
__global__ void __launch_bounds__(256) k_attn(){
    int b = blockIdx.y; int q0 = blockIdx.x * 16;
    __shared__ __half Qs[16][264];
    __shared__ __half Ks[16][264];
    __shared__ __half Gs[16][264];
    __shared__ float Ss[16][17];
    int t = threadIdx.x;
    for (int i8 = t; i8 < 16*32; i8 += 256){
        int r = i8 >> 5, c8 = (i8 & 31)*8;
        *(uint4*)&Qs[r][c8] = *(const uint4*)&d_qh[((size_t)(b*Nn) + q0 + r)*256 + c8];
    }
    int cnt = d_cnt[b];
    int q = t >> 4, lane = t & 15;
    float yacc[16];
    #pragma unroll
    for (int i=0;i<16;i++) yacc[i] = 0.f;
    float rmax = -1e30f, rsum = 0.f;
    __syncthreads();
    for (int j0=0; j0<cnt; j0+=16){
        int jn = min(16, cnt - j0);
        for (int i8 = t; i8 < jn*32; i8 += 256){
            int r = i8 >> 5, c8 = (i8 & 31)*8;
            int src = d_act[b*Nn + j0 + r];
            size_t base = ((size_t)(b*Nn) + src)*256 + c8;
            *(uint4*)&Ks[r][c8] = *(const uint4*)&d_kh[base];
            *(uint4*)&Gs[r][c8] = *(const uint4*)&d_gh[base];
        }
        __syncthreads();
        float s = -1e30f;
        if (lane < jn){
            s = 0.f;
            #pragma unroll 4
            for (int c8 = 0; c8 < 32; c8++){
                uint4 qv = *(const uint4*)&Qs[q][c8*8];
                uint4 kv = *(const uint4*)&Ks[lane][c8*8];
                const __half2* qh = (const __half2*)&qv;
                const __half2* kh = (const __half2*)&kv;
                #pragma unroll
                for (int j = 0; j < 4; j++){
                    float2 a = __half22float2(qh[j]);
                    float2 bb = __half22float2(kh[j]);
                    s += a.x*bb.x + a.y*bb.y;
                }
            }
        }
        Ss[q][lane] = s;
        __syncthreads();
        float cmax = rmax;
        for (int j=0;j<jn;j++) cmax = fmaxf(cmax, Ss[q][j]);
        float scale = __expf(rmax - cmax);
        rsum *= scale;
        #pragma unroll
        for (int i=0;i<16;i++) yacc[i] *= scale;
        for (int j=0;j<jn;j++){
            float pj = __expf(Ss[q][j] - cmax);
            rsum += pj;
            #pragma unroll
            for (int i=0;i<16;i++) yacc[i] += pj * __half2float(Gs[j][lane + i*16]);
        }
        rmax = cmax;
        __syncthreads();
    }
    float inv = (rsum > 0.f) ? (1.f/rsum) : 0.f;
    #pragma unroll
    for (int i=0;i<16;i++)
        d_ph[((size_t)(b*Nn) + q0 + q)*256 + lane + i*16] = __float2half(yacc[i]*inv);
}

// ---------------- instance-norm finalize (reads+zeros psum) ----------------
__global__ void k_statf(){
    int b = blockIdx.x, c = threadIdx.x;
    float s  = d_psum[b*256 + c];
    float s2 = d_psum[1024 + b*256 + c];
    float mu = s * (1.f/4096.f);
    float var = s2 * (1.f/4096.f) - mu*mu;
    d_mean[b*256+c] = mu;
    d_rstd[b*256+c] = rsqrtf(var + 1e-5f);
    d_psum[b*256 + c] = 0.f;
    d_psum[1024 + b*256 + c] = 0.f;
}

// relu(IN(t-planes)) -> p-hi plane
__global__ void k_in_relu(){
    int i2 = blockIdx.x*256 + threadIdx.x;
    int base = i2*2;
    int c = base & 255; int b = base >> 20;
    __half2 h2 = *(const __half2*)&d_th[base];
    __half2 l2 = *(const __half2*)&d_tl[base];
    float v0 = __half2float(h2.x) + __half2float(l2.x);
    float v1 = __half2float(h2.y) + __half2float(l2.y);
    v0 = fmaxf((v0 - d_mean[b*256+c])   * d_rstd[b*256+c],   0.f);
    v1 = fmaxf((v1 - d_mean[b*256+c+1]) * d_rstd[b*256+c+1], 0.f);
    *(__half2*)&d_ph[base] = __halves2half2(__float2half(v0), __float2half(v1));
}
// wyh += IN(t-planes), stored fp16
__global__ void k_in_add(){
    int i2 = blockIdx.x*256 + threadIdx.x;
    int base = i2*2;
    int c = base & 255; int b = base >> 20;
    __half2 h2 = *(const __half2*)&d_th[base];
    __half2 l2 = *(const __half2*)&d_tl[base];
    float v0 = __half2float(h2.x) + __half2float(l2.x);
    float v1 = __half2float(h2.y) + __half2float(l2.y);
    __half2 w2 = *(const __half2*)&d_wyh[base];
    float w0 = __half2float(w2.x) + (v0 - d_mean[b*256+c])   * d_rstd[b*256+c];
    float w1 = __half2float(w2.y) + (v1 - d_mean[b*256+c+1]) * d_rstd[b*256+c+1];
    *(__half2*)&d_wyh[base] = __halves2half2(__float2half(w0), __float2half(w1));
}

// ---------------- final blend + NHWC->NCHW ----------------
__global__ void k_blend(const float* __restrict__ x, float* __restrict__ z){
    __shared__ float tile[32][33];
    int b = blockIdx.z; int n0 = blockIdx.x*32, c0 = blockIdx.y*32;
    int tx = threadIdx.x, ty = threadIdx.y;
    tile[ty][tx] = __half2float(d_wyh[((size_t)(b*Nn) + n0+ty)*256 + c0+tx]);
    __syncthreads();
    int n = n0 + tx, c = c0 + ty;
    float m = d_mk[b*Nn + n];
    size_t idx = ((size_t)(b*Cc + c))*Nn + n;
    z[idx] = m * x[idx] + (1.f - m) * tile[tx][ty];
}

// ---------------- launch ----------------
extern "C" void kernel_launch(void* const* d_in, const int* in_sizes, int n_in,
                              void* d_out, int out_size) {
    (void)in_sizes; (void)n_in; (void)out_size;
    const float* x    = (const float*)d_in[0];
    const float* mask = (const float*)d_in[1];
    const float* g_w  = (const float*)d_in[2];
    const float* g_b  = (const float*)d_in[3];
    const float* th_w = (const float*)d_in[4];
    const float* th_b = (const float*)d_in[5];
    const float* ph_w = (const float*)d_in[6];
    const float* ph_b = (const float*)d_in[7];
    const float* W_w  = (const float*)d_in[8];
    const float* W_b  = (const float*)d_in[9];
    const float* rw1  = (const float*)d_in[10];
    const float* rb1  = (const float*)d_in[11];
    const float* rw2  = (const float*)d_in[12];
    const float* rb2  = (const float*)d_in[13];
    float* z = (float*)d_out;

    cudaFuncSetAttribute(k_tmm,  cudaFuncAttributeMaxDynamicSharedMemorySize, TM_SMEM_TOTAL);
    cudaFuncSetAttribute(k_tmmc, cudaFuncAttributeMaxDynamicSharedMemorySize, TC_SMEM_TOTAL);

    float *pps;
    __half *pqh, *pkh, *pgh, *pwyh, *pah, *pal, *pph, *pth, *ptl, *pwbh, *pwbl, *pw1h, *pw1l;
    cudaGetSymbolAddress((void**)&pqh, d_qh);
    cudaGetSymbolAddress((void**)&pkh, d_kh);
    cudaGetSymbolAddress((void**)&pgh, d_gh);
    cudaGetSymbolAddress((void**)&pps, d_psum);
    cudaGetSymbolAddress((void**)&pwyh, d_wyh);
    cudaGetSymbolAddress((void**)&pah, d_ah);
    cudaGetSymbolAddress((void**)&pal, d_al);
    cudaGetSymbolAddress((void**)&pph, d_ph);
    cudaGetSymbolAddress((void**)&pth, d_th);
    cudaGetSymbolAddress((void**)&ptl, d_tl);
    cudaGetSymbolAddress((void**)&pwbh, d_wbh);
    cudaGetSymbolAddress((void**)&pwbl, d_wbl);
    cudaGetSymbolAddress((void**)&pw1h, d_w1h);
    cudaGetSymbolAddress((void**)&pw1l, d_w1l);

    dim3 t32(32,32);
    k_wconvr<<<768, 256>>>(rw1, rw2);
    k_wconv1<<<1024, 256>>>(g_w, th_w, ph_w, W_w);
    k_xt  <<<dim3(128,8,4), t32>>>(x);
    k_mask<<<4, 1024>>>(mask);

    dim3 gg(2,128);
    k_tmm<<<gg,256,TM_SMEM_TOTAL>>>(pah, pal, pw1h+1*65536, pw1l+1*65536, th_b, pqh);
    k_tmm<<<gg,256,TM_SMEM_TOTAL>>>(pah, pal, pw1h+2*65536, pw1l+2*65536, ph_b, pkh);
    k_tmm<<<gg,256,TM_SMEM_TOTAL>>>(pah, pal, pw1h+0*65536, pw1l+0*65536, g_b,  pgh);

    k_attn<<<dim3(256,4),256>>>();   // -> d_ph

    // W 1x1 (2-term): p-hi -> wyh
    k_tmmc<<<gg,256,TC_SMEM_TOTAL>>>(pph, pw1h+3*65536, pw1l+3*65536, W_b, pwyh, 0, 0, 1);

    for (int i=0;i<3;i++){
        k_tmmc<<<gg,256,TC_SMEM_TOTAL>>>(pwyh, pwbh + (size_t)(2*i)*9*65536,
                                         pwbl + (size_t)(2*i)*9*65536, rb1 + i*256,
                                         pth, ptl, pps, 9);
        k_statf<<<4,256>>>();
        k_in_relu<<<8192,256>>>();
        k_tmmc<<<gg,256,TC_SMEM_TOTAL>>>(pph, pwbh + (size_t)(2*i+1)*9*65536,
                                         pwbl + (size_t)(2*i+1)*9*65536, rb2 + i*256,
                                         pth, ptl, pps, 9);
        k_statf<<<4,256>>>();
        k_in_add<<<8192,256>>>();
    }

    k_blend<<<dim3(128,8,4), t32>>>(x, z);
}